// round 2
// baseline (speedup 1.0000x reference)
#include <cuda_runtime.h>

#define NN 50000
#define EE 250000
#define HH 4
#define CC 64
#define DNODE 256
#define EDD 194

// ---------------- scratch (device globals; no runtime allocation) ----------------
__device__ float g_q [(size_t)NN * DNODE];
__device__ float g_k [(size_t)NN * DNODE];
__device__ float g_v [(size_t)NN * DNODE];
__device__ float g_x1[(size_t)NN * DNODE];   // layer-1 agg+skip, then relu'd input to layer 2
__device__ float g_e [(size_t)EE * DNODE];   // edge embeddings
__device__ float g_ex[(size_t)EE * HH];      // logits, then exp values
__device__ int   g_m [(size_t)NN * HH];      // segment max (ordered-int encoding)
__device__ float g_den[(size_t)NN * HH];     // segment sum of exp

// ---------------- SGEMM: C[M,256] = A[M,K] @ B[K,256] (+bias) ----------------
// 128x128 block tile, BK=8, 256 threads, 8x8 microtile.
// A rows may be arbitrarily aligned (K=194 case) -> scalar A loads.
__global__ __launch_bounds__(256) void sgemm_bias(
    const float* __restrict__ A, const float* __restrict__ B,
    const float* __restrict__ bias, float* __restrict__ C,
    int M, int K)
{
    __shared__ float As[8][128];
    __shared__ float Bs[8][128];

    const int tid  = threadIdx.x;
    const int tx   = tid & 15;     // 16 col groups
    const int ty   = tid >> 4;     // 16 row groups
    const int row0 = blockIdx.y * 128;
    const int col0 = blockIdx.x * 128;

    float acc[8][8];
#pragma unroll
    for (int i = 0; i < 8; i++)
#pragma unroll
        for (int j = 0; j < 8; j++) acc[i][j] = 0.f;

    // A tile load mapping: 2 threads per row, 4 scalars each (128 rows x 8 k)
    const int arow = tid >> 1;
    const int akk  = (tid & 1) * 4;
    // B tile load mapping: coalesced float4 (8 k-rows x 128 cols)
    const int bk   = tid >> 5;
    const int bn4  = (tid & 31) * 4;

    for (int k0 = 0; k0 < K; k0 += 8) {
        // ---- load A tile (scalar: A row base may be 8B-misaligned when K=194) ----
        {
            int gm = row0 + arow;
            int gk = k0 + akk;
            float a0 = 0.f, a1 = 0.f, a2 = 0.f, a3 = 0.f;
            if (gm < M) {
                const float* ap = A + (size_t)gm * K;
                if (gk + 0 < K) a0 = __ldg(ap + gk + 0);
                if (gk + 1 < K) a1 = __ldg(ap + gk + 1);
                if (gk + 2 < K) a2 = __ldg(ap + gk + 2);
                if (gk + 3 < K) a3 = __ldg(ap + gk + 3);
            }
            As[akk + 0][arow] = a0;
            As[akk + 1][arow] = a1;
            As[akk + 2][arow] = a2;
            As[akk + 3][arow] = a3;
        }
        // ---- load B tile (coalesced, stride 256 floats -> 16B aligned) ----
        {
            int gk = k0 + bk;
            float4 bv = make_float4(0.f, 0.f, 0.f, 0.f);
            if (gk < K) bv = *(const float4*)(B + (size_t)gk * 256 + col0 + bn4);
            *(float4*)&Bs[bk][bn4] = bv;
        }
        __syncthreads();

#pragma unroll
        for (int kk = 0; kk < 8; kk++) {
            float4 a0 = *(const float4*)&As[kk][ty * 4];
            float4 a1 = *(const float4*)&As[kk][64 + ty * 4];
            float4 b0 = *(const float4*)&Bs[kk][tx * 4];
            float4 b1 = *(const float4*)&Bs[kk][64 + tx * 4];
            float ar[8] = {a0.x, a0.y, a0.z, a0.w, a1.x, a1.y, a1.z, a1.w};
            float br[8] = {b0.x, b0.y, b0.z, b0.w, b1.x, b1.y, b1.z, b1.w};
#pragma unroll
            for (int i = 0; i < 8; i++)
#pragma unroll
                for (int j = 0; j < 8; j++)
                    acc[i][j] += ar[i] * br[j];
        }
        __syncthreads();
    }

    // ---- epilogue: bias + store (two float4 per row) ----
    float bj[8];
#pragma unroll
    for (int j = 0; j < 8; j++) {
        int gc = col0 + ((j < 4) ? (tx * 4 + j) : (64 + tx * 4 + j - 4));
        bj[j] = bias ? bias[gc] : 0.f;
    }
#pragma unroll
    for (int i = 0; i < 8; i++) {
        int gm = row0 + ((i < 4) ? (ty * 4 + i) : (64 + ty * 4 + i - 4));
        if (gm >= M) continue;
        float4 o0 = make_float4(acc[i][0] + bj[0], acc[i][1] + bj[1],
                                acc[i][2] + bj[2], acc[i][3] + bj[3]);
        float4 o1 = make_float4(acc[i][4] + bj[4], acc[i][5] + bj[5],
                                acc[i][6] + bj[6], acc[i][7] + bj[7]);
        *(float4*)(C + (size_t)gm * 256 + col0 + tx * 4)      = o0;
        *(float4*)(C + (size_t)gm * 256 + col0 + 64 + tx * 4) = o1;
    }
}

// ---------------- helpers ----------------
__device__ __forceinline__ int enc_f(float f) {
    int i = __float_as_int(f);
    return (i >= 0) ? i : (i ^ 0x7fffffff);
}
__device__ __forceinline__ float dec_f(int e) {
    int raw = (e >= 0) ? e : (e ^ 0x7fffffff);
    return __int_as_float(raw);
}

__global__ void init_seg(int* __restrict__ m, float* __restrict__ den, int n) {
    int i = blockIdx.x * blockDim.x + threadIdx.x;
    if (i < n) { m[i] = 0x80000000; den[i] = 0.f; }
}

// Pass A: per (edge, head) logit + segment max
__global__ void edge_logits(const float* __restrict__ q, const float* __restrict__ k,
                            const float* __restrict__ eemb,
                            const int* __restrict__ src, const int* __restrict__ dst,
                            float* __restrict__ logit, int* __restrict__ mmax)
{
    int idx = blockIdx.x * blockDim.x + threadIdx.x;
    if (idx >= EE * HH) return;
    int e = idx >> 2, h = idx & 3;
    int s = src[e], d = dst[e];
    const float4* qp = (const float4*)(q    + (size_t)d * DNODE + h * CC);
    const float4* kp = (const float4*)(k    + (size_t)s * DNODE + h * CC);
    const float4* ep = (const float4*)(eemb + (size_t)e * DNODE + h * CC);
    float acc = 0.f;
#pragma unroll
    for (int i = 0; i < 16; i++) {
        float4 a = qp[i], b = kp[i], c = ep[i];
        acc += a.x * (b.x + c.x) + a.y * (b.y + c.y)
             + a.z * (b.z + c.z) + a.w * (b.w + c.w);
    }
    float lg = acc * 0.125f;   // 1/sqrt(64)
    logit[idx] = lg;
    atomicMax(&mmax[d * HH + h], enc_f(lg));
}

// Pass B: exp(logit - max) + segment denom
__global__ void edge_exp(const int* __restrict__ dst,
                         float* __restrict__ logit,
                         const int* __restrict__ mmax,
                         float* __restrict__ den)
{
    int idx = blockIdx.x * blockDim.x + threadIdx.x;
    if (idx >= EE * HH) return;
    int e = idx >> 2, h = idx & 3;
    int d = dst[e];
    float m = dec_f(mmax[d * HH + h]);
    float ex = __expf(logit[idx] - m);
    logit[idx] = ex;
    atomicAdd(&den[d * HH + h], ex);
}

// Pass C: weighted scatter of (v[src]+e) into agg (vectorized reductions)
__global__ void edge_agg(const float* __restrict__ v, const float* __restrict__ eemb,
                         const int* __restrict__ src, const int* __restrict__ dst,
                         const float* __restrict__ exv, const float* __restrict__ den,
                         float* __restrict__ agg)
{
    int idx = blockIdx.x * blockDim.x + threadIdx.x;
    if (idx >= EE * 64) return;         // E * H * (C/4)
    int c4 = idx & 15;
    int h  = (idx >> 4) & 3;
    int e  = idx >> 6;
    int s = src[e], d = dst[e];
    float a = exv[e * HH + h] / (den[d * HH + h] + 1e-16f);
    int off = h * CC + c4 * 4;
    float4 vv = *(const float4*)(v    + (size_t)s * DNODE + off);
    float4 ev = *(const float4*)(eemb + (size_t)e * DNODE + off);
    float4 r = make_float4((vv.x + ev.x) * a, (vv.y + ev.y) * a,
                           (vv.z + ev.z) * a, (vv.w + ev.w) * a);
    float* addr = agg + (size_t)d * DNODE + off;
    asm volatile("red.global.add.v4.f32 [%0], {%1, %2, %3, %4};"
                 :: "l"(addr), "f"(r.x), "f"(r.y), "f"(r.z), "f"(r.w) : "memory");
}

__global__ void relu_inplace(float* __restrict__ x, int n) {
    int i = blockIdx.x * blockDim.x + threadIdx.x;
    if (i < n) x[i] = fmaxf(x[i], 0.f);
}

// ---------------- host side ----------------
static void run_layer(const float* xin, const float* edge_attr,
                      const int* src, const int* dst,
                      const float* Wq, const float* bq,
                      const float* Wk, const float* bk,
                      const float* Wv, const float* bv,
                      const float* We,
                      const float* Ws, const float* bs,
                      float* q, float* k, float* v, float* e,
                      float* ex, int* m, float* den,
                      float* agg /* receives skip + aggregation */)
{
    dim3 blk(256);
    dim3 gn(2, (NN + 127) / 128);
    dim3 ge(2, (EE + 127) / 128);

    sgemm_bias<<<gn, blk>>>(xin, Wq, bq, q,   NN, DNODE);
    sgemm_bias<<<gn, blk>>>(xin, Wk, bk, k,   NN, DNODE);
    sgemm_bias<<<gn, blk>>>(xin, Wv, bv, v,   NN, DNODE);
    sgemm_bias<<<gn, blk>>>(xin, Ws, bs, agg, NN, DNODE);
    sgemm_bias<<<ge, blk>>>(edge_attr, We, nullptr, e, EE, EDD);

    init_seg<<<(NN * HH + 255) / 256, blk>>>(m, den, NN * HH);
    edge_logits<<<(EE * HH + 255) / 256, blk>>>(q, k, e, src, dst, ex, m);
    edge_exp<<<(EE * HH + 255) / 256, blk>>>(dst, ex, m, den);
    edge_agg<<<(EE * 64 + 255) / 256, blk>>>(v, e, src, dst, ex, den, agg);
}

extern "C" void kernel_launch(void* const* d_in, const int* in_sizes, int n_in,
                              void* d_out, int out_size)
{
    const float* x   = (const float*)d_in[0];
    const int*   ei  = (const int*)  d_in[1];
    const float* ea  = (const float*)d_in[2];
    const float* Wq1 = (const float*)d_in[3];
    const float* bq1 = (const float*)d_in[4];
    const float* Wk1 = (const float*)d_in[5];
    const float* bk1 = (const float*)d_in[6];
    const float* Wv1 = (const float*)d_in[7];
    const float* bv1 = (const float*)d_in[8];
    const float* We1 = (const float*)d_in[9];
    const float* Ws1 = (const float*)d_in[10];
    const float* bs1 = (const float*)d_in[11];
    const float* Wq2 = (const float*)d_in[12];
    const float* bq2 = (const float*)d_in[13];
    const float* Wk2 = (const float*)d_in[14];
    const float* bk2 = (const float*)d_in[15];
    const float* Wv2 = (const float*)d_in[16];
    const float* bv2 = (const float*)d_in[17];
    const float* We2 = (const float*)d_in[18];
    const float* Ws2 = (const float*)d_in[19];
    const float* bs2 = (const float*)d_in[20];

    const int* src = ei;
    const int* dst = ei + EE;
    float* out = (float*)d_out;

    float *q, *k, *v, *x1, *e, *ex, *den;
    int* m;
    cudaGetSymbolAddress((void**)&q,   g_q);
    cudaGetSymbolAddress((void**)&k,   g_k);
    cudaGetSymbolAddress((void**)&v,   g_v);
    cudaGetSymbolAddress((void**)&x1,  g_x1);
    cudaGetSymbolAddress((void**)&e,   g_e);
    cudaGetSymbolAddress((void**)&ex,  g_ex);
    cudaGetSymbolAddress((void**)&m,   g_m);
    cudaGetSymbolAddress((void**)&den, g_den);

    // ---- layer 1: h = relu(tconv(x)) ----
    run_layer(x, ea, src, dst,
              Wq1, bq1, Wk1, bk1, Wv1, bv1, We1, Ws1, bs1,
              q, k, v, e, ex, m, den, x1);
    relu_inplace<<<(NN * DNODE + 255) / 256, 256>>>(x1, NN * DNODE);

    // ---- layer 2: out = tconv(h), agg accumulates directly into d_out ----
    run_layer(x1, ea, src, dst,
              Wq2, bq2, Wk2, bk2, Wv2, bv2, We2, Ws2, bs2,
              q, k, v, e, ex, m, den, out);
}

// round 5
// speedup vs baseline: 1.3733x; 1.3733x over previous
#include <cuda_runtime.h>
#include <cuda_bf16.h>
#include <cstdint>

#define NN 50000
#define EE 250000
#define HH 4
#define CC 64
#define DNODE 256
#define EDD 194
#define KPAD 256
#define NOUT 256

// ---------------- scratch (device globals; no runtime allocation) ----------------
__device__ float g_q [(size_t)NN * DNODE];
__device__ float g_k [(size_t)NN * DNODE];
__device__ float g_v [(size_t)NN * DNODE];
__device__ float g_x1[(size_t)NN * DNODE];
__device__ float g_e [(size_t)EE * DNODE];
__device__ float g_ex[(size_t)EE * HH];
__device__ int   g_m [(size_t)NN * HH];
__device__ float g_den[(size_t)NN * HH];

// split-bf16 operand buffers
__device__ __nv_bfloat16 g_ahi[(size_t)NN * KPAD];
__device__ __nv_bfloat16 g_alo[(size_t)NN * KPAD];
__device__ __nv_bfloat16 g_ehi[(size_t)EE * KPAD];
__device__ __nv_bfloat16 g_elo[(size_t)EE * KPAD];
__device__ __nv_bfloat16 g_whi[10][(size_t)NOUT * KPAD];   // [n][k], transposed + k-padded
__device__ __nv_bfloat16 g_wlo[10][(size_t)NOUT * KPAD];

// ==================== split-bf16 HMMA GEMM ====================
// C[M,256] = A[M,256] @ W^T (W stored [256 n][256 k]) + bias
// A,W given as bf16 hi/lo splits; 3-product accumulation in fp32.
// 128x128 block tile (grid.y covers the 2 N tiles), 8 warps (2m x 4n), BK=32.
#define BM 128
#define BN 128
#define BK 32
#define LDS_A 40   // padded smem stride (bf16 elems); 40*2=80B, rows stay 16B-aligned

__device__ __forceinline__ void mma_bf16(float* c, const uint32_t* a, const uint32_t* b) {
    asm volatile(
        "mma.sync.aligned.m16n8k16.row.col.f32.bf16.bf16.f32 "
        "{%0,%1,%2,%3}, {%4,%5,%6,%7}, {%8,%9}, {%0,%1,%2,%3};"
        : "+f"(c[0]), "+f"(c[1]), "+f"(c[2]), "+f"(c[3])
        : "r"(a[0]), "r"(a[1]), "r"(a[2]), "r"(a[3]), "r"(b[0]), "r"(b[1]));
}

__global__ __launch_bounds__(256) void gemm_split(
    const __nv_bfloat16* __restrict__ Ahi, const __nv_bfloat16* __restrict__ Alo,
    const __nv_bfloat16* __restrict__ Bhi, const __nv_bfloat16* __restrict__ Blo,
    const float* __restrict__ bias, float* __restrict__ C, int M)
{
    __shared__ __nv_bfloat16 sAhi[BM * LDS_A];
    __shared__ __nv_bfloat16 sAlo[BM * LDS_A];
    __shared__ __nv_bfloat16 sBhi[BN * LDS_A];
    __shared__ __nv_bfloat16 sBlo[BN * LDS_A];

    const int tid  = threadIdx.x;
    const int wid  = tid >> 5;
    const int lane = tid & 31;
    const int m0   = blockIdx.x * BM;
    const int n0   = blockIdx.y * BN;

    const int wm = (wid & 1) * 64;   // warp m offset
    const int wn = (wid >> 1) * 32;  // warp n offset

    const int gr  = lane >> 2;       // groupID
    const int tig = lane & 3;        // thread-in-group

    float acc[4][4][4];
#pragma unroll
    for (int i = 0; i < 4; i++)
#pragma unroll
        for (int j = 0; j < 4; j++)
#pragma unroll
            for (int r = 0; r < 4; r++) acc[i][j][r] = 0.f;

    // global->smem mapping: 128 rows x 32 cols bf16 per tile; 2 uint4 per thread
    const int r0  = tid >> 1;
    const int cg0 = (tid & 1) * 8;
    for (int kc = 0; kc < KPAD; kc += BK) {
#pragma unroll
        for (int half = 0; half < 2; half++) {
            int row = r0;
            int col = cg0 + half * 16;
            int gm = m0 + row;
            uint4 vh = make_uint4(0,0,0,0), vl = make_uint4(0,0,0,0);
            if (gm < M) {
                vh = *(const uint4*)(Ahi + (size_t)gm * KPAD + kc + col);
                vl = *(const uint4*)(Alo + (size_t)gm * KPAD + kc + col);
            }
            *(uint4*)(sAhi + row * LDS_A + col) = vh;
            *(uint4*)(sAlo + row * LDS_A + col) = vl;
            *(uint4*)(sBhi + row * LDS_A + col) = *(const uint4*)(Bhi + (size_t)(n0 + row) * KPAD + kc + col);
            *(uint4*)(sBlo + row * LDS_A + col) = *(const uint4*)(Blo + (size_t)(n0 + row) * KPAD + kc + col);
        }
        __syncthreads();

#pragma unroll
        for (int ks = 0; ks < BK; ks += 16) {
            uint32_t ah[4][4], al[4][4];
#pragma unroll
            for (int mt = 0; mt < 4; mt++) {
                int mr = wm + mt * 16;
                int c = ks + tig * 2;
                ah[mt][0] = *(const uint32_t*)(sAhi + (mr + gr)     * LDS_A + c);
                ah[mt][1] = *(const uint32_t*)(sAhi + (mr + gr + 8) * LDS_A + c);
                ah[mt][2] = *(const uint32_t*)(sAhi + (mr + gr)     * LDS_A + c + 8);
                ah[mt][3] = *(const uint32_t*)(sAhi + (mr + gr + 8) * LDS_A + c + 8);
                al[mt][0] = *(const uint32_t*)(sAlo + (mr + gr)     * LDS_A + c);
                al[mt][1] = *(const uint32_t*)(sAlo + (mr + gr + 8) * LDS_A + c);
                al[mt][2] = *(const uint32_t*)(sAlo + (mr + gr)     * LDS_A + c + 8);
                al[mt][3] = *(const uint32_t*)(sAlo + (mr + gr + 8) * LDS_A + c + 8);
            }
            uint32_t bh[4][2], bl[4][2];
#pragma unroll
            for (int nt = 0; nt < 4; nt++) {
                int nr = wn + nt * 8 + gr;
                int c = ks + tig * 2;
                bh[nt][0] = *(const uint32_t*)(sBhi + nr * LDS_A + c);
                bh[nt][1] = *(const uint32_t*)(sBhi + nr * LDS_A + c + 8);
                bl[nt][0] = *(const uint32_t*)(sBlo + nr * LDS_A + c);
                bl[nt][1] = *(const uint32_t*)(sBlo + nr * LDS_A + c + 8);
            }
#pragma unroll
            for (int mt = 0; mt < 4; mt++)
#pragma unroll
                for (int nt = 0; nt < 4; nt++) {
                    mma_bf16(acc[mt][nt], ah[mt], bh[nt]);
                    mma_bf16(acc[mt][nt], ah[mt], bl[nt]);
                    mma_bf16(acc[mt][nt], al[mt], bh[nt]);
                }
        }
        __syncthreads();
    }

    // ---- epilogue: direct global stores (float2 per frag-row) + bias ----
#pragma unroll
    for (int nt = 0; nt < 4; nt++) {
        int gc = n0 + wn + nt * 8 + tig * 2;
        float2 b2 = bias ? *(const float2*)(bias + gc) : make_float2(0.f, 0.f);
#pragma unroll
        for (int mt = 0; mt < 4; mt++) {
            int gm = m0 + wm + mt * 16 + gr;
            if (gm < M) {
                float2 v0 = make_float2(acc[mt][nt][0] + b2.x, acc[mt][nt][1] + b2.y);
                *(float2*)(C + (size_t)gm * NOUT + gc) = v0;
            }
            if (gm + 8 < M) {
                float2 v1 = make_float2(acc[mt][nt][2] + b2.x, acc[mt][nt][3] + b2.y);
                *(float2*)(C + (size_t)(gm + 8) * NOUT + gc) = v1;
            }
        }
    }
}

// ==================== conversion kernels ====================
__global__ void split_feat(const float* __restrict__ X,
                           __nv_bfloat16* __restrict__ hi, __nv_bfloat16* __restrict__ lo,
                           int M, int Kin, int do_relu)
{
    int idx = blockIdx.x * blockDim.x + threadIdx.x;
    if (idx >= M * KPAD) return;
    int k = idx & (KPAD - 1);
    float v = 0.f;
    if (k < Kin) v = X[(size_t)(idx >> 8) * Kin + k];
    if (do_relu) v = fmaxf(v, 0.f);
    __nv_bfloat16 h = __float2bfloat16(v);
    hi[idx] = h;
    lo[idx] = __float2bfloat16(v - __bfloat162float(h));
}

__global__ void split_weight(const float* __restrict__ W,
                             __nv_bfloat16* __restrict__ hi, __nv_bfloat16* __restrict__ lo,
                             int Kin)
{
    int idx = blockIdx.x * blockDim.x + threadIdx.x;
    if (idx >= NOUT * KPAD) return;
    int n = idx & 255, k = idx >> 8;
    float v = (k < Kin) ? W[(size_t)k * NOUT + n] : 0.f;
    __nv_bfloat16 h = __float2bfloat16(v);
    hi[(size_t)n * KPAD + k] = h;
    lo[(size_t)n * KPAD + k] = __float2bfloat16(v - __bfloat162float(h));
}

// ==================== edge attention ====================
__device__ __forceinline__ int enc_f(float f) {
    int i = __float_as_int(f);
    return (i >= 0) ? i : (i ^ 0x7fffffff);
}
__device__ __forceinline__ float dec_f(int e) {
    int raw = (e >= 0) ? e : (e ^ 0x7fffffff);
    return __int_as_float(raw);
}

__global__ void init_seg(int* __restrict__ m, float* __restrict__ den, int n) {
    int i = blockIdx.x * blockDim.x + threadIdx.x;
    if (i < n) { m[i] = 0x80000000; den[i] = 0.f; }
}

__global__ void edge_logits(const float* __restrict__ q, const float* __restrict__ k,
                            const float* __restrict__ eemb,
                            const int* __restrict__ src, const int* __restrict__ dst,
                            float* __restrict__ logit, int* __restrict__ mmax)
{
    int idx = blockIdx.x * blockDim.x + threadIdx.x;
    if (idx >= EE * HH) return;
    int e = idx >> 2, h = idx & 3;
    int s = src[e], d = dst[e];
    const float4* qp = (const float4*)(q    + (size_t)d * DNODE + h * CC);
    const float4* kp = (const float4*)(k    + (size_t)s * DNODE + h * CC);
    const float4* ep = (const float4*)(eemb + (size_t)e * DNODE + h * CC);
    float acc = 0.f;
#pragma unroll
    for (int i = 0; i < 16; i++) {
        float4 a = qp[i], b = kp[i], c = ep[i];
        acc += a.x * (b.x + c.x) + a.y * (b.y + c.y)
             + a.z * (b.z + c.z) + a.w * (b.w + c.w);
    }
    float lg = acc * 0.125f;
    logit[idx] = lg;
    atomicMax(&mmax[d * HH + h], enc_f(lg));
}

__global__ void edge_exp(const int* __restrict__ dst,
                         float* __restrict__ logit,
                         const int* __restrict__ mmax,
                         float* __restrict__ den)
{
    int idx = blockIdx.x * blockDim.x + threadIdx.x;
    if (idx >= EE * HH) return;
    int e = idx >> 2, h = idx & 3;
    int d = dst[e];
    float m = dec_f(mmax[d * HH + h]);
    float ex = __expf(logit[idx] - m);
    logit[idx] = ex;
    atomicAdd(&den[d * HH + h], ex);
}

__global__ void edge_agg(const float* __restrict__ v, const float* __restrict__ eemb,
                         const int* __restrict__ src, const int* __restrict__ dst,
                         const float* __restrict__ exv, const float* __restrict__ den,
                         float* __restrict__ agg)
{
    int idx = blockIdx.x * blockDim.x + threadIdx.x;
    if (idx >= EE * 64) return;
    int c4 = idx & 15;
    int h  = (idx >> 4) & 3;
    int e  = idx >> 6;
    int s = src[e], d = dst[e];
    float a = exv[e * HH + h] / (den[d * HH + h] + 1e-16f);
    int off = h * CC + c4 * 4;
    float4 vv = *(const float4*)(v    + (size_t)s * DNODE + off);
    float4 ev = *(const float4*)(eemb + (size_t)e * DNODE + off);
    float4 r = make_float4((vv.x + ev.x) * a, (vv.y + ev.y) * a,
                           (vv.z + ev.z) * a, (vv.w + ev.w) * a);
    float* addr = agg + (size_t)d * DNODE + off;
    asm volatile("red.global.add.v4.f32 [%0], {%1, %2, %3, %4};"
                 :: "l"(addr), "f"(r.x), "f"(r.y), "f"(r.z), "f"(r.w) : "memory");
}

// ==================== host side ====================
static void run_layer(const __nv_bfloat16* ahi, const __nv_bfloat16* alo,
                      const __nv_bfloat16* ehi, const __nv_bfloat16* elo,
                      const __nv_bfloat16* whi, const __nv_bfloat16* wlo, size_t wstride,
                      const float* bq, const float* bk, const float* bv, const float* bs,
                      const int* src, const int* dst,
                      float* q, float* k, float* v, float* e,
                      float* ex, int* m, float* den, float* agg)
{
    dim3 gn((NN + BM - 1) / BM, NOUT / BN);
    dim3 ge((EE + BM - 1) / BM, NOUT / BN);
    gemm_split<<<gn, 256>>>(ahi, alo, whi + 0 * wstride, wlo + 0 * wstride, bq, q,   NN);
    gemm_split<<<gn, 256>>>(ahi, alo, whi + 1 * wstride, wlo + 1 * wstride, bk, k,   NN);
    gemm_split<<<gn, 256>>>(ahi, alo, whi + 2 * wstride, wlo + 2 * wstride, bv, v,   NN);
    gemm_split<<<ge, 256>>>(ehi, elo, whi + 3 * wstride, wlo + 3 * wstride, nullptr, e, EE);
    gemm_split<<<gn, 256>>>(ahi, alo, whi + 4 * wstride, wlo + 4 * wstride, bs, agg, NN);

    init_seg<<<(NN * HH + 255) / 256, 256>>>(m, den, NN * HH);
    edge_logits<<<(EE * HH + 255) / 256, 256>>>(q, k, e, src, dst, ex, m);
    edge_exp<<<(EE * HH + 255) / 256, 256>>>(dst, ex, m, den);
    edge_agg<<<(EE * 64 + 255) / 256, 256>>>(v, e, src, dst, ex, den, agg);
}

extern "C" void kernel_launch(void* const* d_in, const int* in_sizes, int n_in,
                              void* d_out, int out_size)
{
    const float* x   = (const float*)d_in[0];
    const int*   ei  = (const int*)  d_in[1];
    const float* ea  = (const float*)d_in[2];
    const float* W1[5] = { (const float*)d_in[3],  (const float*)d_in[5],
                           (const float*)d_in[7],  (const float*)d_in[9],
                           (const float*)d_in[10] };
    const float* b1[4] = { (const float*)d_in[4],  (const float*)d_in[6],
                           (const float*)d_in[8],  (const float*)d_in[11] };
    const float* W2[5] = { (const float*)d_in[12], (const float*)d_in[14],
                           (const float*)d_in[16], (const float*)d_in[18],
                           (const float*)d_in[19] };
    const float* b2[4] = { (const float*)d_in[13], (const float*)d_in[15],
                           (const float*)d_in[17], (const float*)d_in[20] };
    const int Kin[5] = { DNODE, DNODE, DNODE, EDD, DNODE };

    const int* src = ei;
    const int* dst = ei + EE;
    float* out = (float*)d_out;

    float *q, *k, *v, *x1, *e, *ex, *den;
    int* m;
    __nv_bfloat16 *ahi, *alo, *ehi, *elo, *whi, *wlo;
    cudaGetSymbolAddress((void**)&q,   g_q);
    cudaGetSymbolAddress((void**)&k,   g_k);
    cudaGetSymbolAddress((void**)&v,   g_v);
    cudaGetSymbolAddress((void**)&x1,  g_x1);
    cudaGetSymbolAddress((void**)&e,   g_e);
    cudaGetSymbolAddress((void**)&ex,  g_ex);
    cudaGetSymbolAddress((void**)&m,   g_m);
    cudaGetSymbolAddress((void**)&den, g_den);
    cudaGetSymbolAddress((void**)&ahi, g_ahi);
    cudaGetSymbolAddress((void**)&alo, g_alo);
    cudaGetSymbolAddress((void**)&ehi, g_ehi);
    cudaGetSymbolAddress((void**)&elo, g_elo);
    cudaGetSymbolAddress((void**)&whi, g_whi);
    cudaGetSymbolAddress((void**)&wlo, g_wlo);
    const size_t WS = (size_t)NOUT * KPAD;

    for (int i = 0; i < 5; i++) {
        split_weight<<<(NOUT * KPAD + 255) / 256, 256>>>(W1[i], whi + i * WS,       wlo + i * WS,       Kin[i]);
        split_weight<<<(NOUT * KPAD + 255) / 256, 256>>>(W2[i], whi + (5 + i) * WS, wlo + (5 + i) * WS, Kin[i]);
    }
    split_feat<<<((size_t)EE * KPAD + 255) / 256, 256>>>(ea, ehi, elo, EE, EDD, 0);
    split_feat<<<((size_t)NN * KPAD + 255) / 256, 256>>>(x,  ahi, alo, NN, DNODE, 0);

    // ---- layer 1 ----
    run_layer(ahi, alo, ehi, elo, whi, wlo, WS,
              b1[0], b1[1], b1[2], b1[3], src, dst,
              q, k, v, e, ex, m, den, x1);

    // relu + re-split x1 as layer-2 input
    split_feat<<<((size_t)NN * KPAD + 255) / 256, 256>>>(x1, ahi, alo, NN, DNODE, 1);

    // ---- layer 2 ----
    run_layer(ahi, alo, ehi, elo, whi + 5 * WS, wlo + 5 * WS, WS,
              b2[0], b2[1], b2[2], b2[3], src, dst,
              q, k, v, e, ex, m, den, out);
}

// round 6
// speedup vs baseline: 1.4852x; 1.0815x over previous
#include <cuda_runtime.h>
#include <cuda_bf16.h>
#include <cstdint>

#define NN 50000
#define EE 250000
#define HH 4
#define CC 64
#define DNODE 256
#define EDD 194
#define KPAD 256
#define NOUT 256

// ---------------- scratch (device globals; no runtime allocation) ----------------
__device__ float g_q [(size_t)NN * DNODE];
__device__ float g_k [(size_t)NN * DNODE];
__device__ float g_v [(size_t)NN * DNODE];
__device__ float g_x1[(size_t)NN * DNODE];
__device__ float g_e [(size_t)EE * DNODE];
__device__ float g_ex[(size_t)EE * HH];
__device__ int   g_m [(size_t)NN * HH];
__device__ float g_den[(size_t)NN * HH];

// split-bf16 operand buffers
__device__ __nv_bfloat16 g_ahi[(size_t)NN * KPAD];
__device__ __nv_bfloat16 g_alo[(size_t)NN * KPAD];
__device__ __nv_bfloat16 g_ehi[(size_t)EE * KPAD];
__device__ __nv_bfloat16 g_elo[(size_t)EE * KPAD];
__device__ __nv_bfloat16 g_whi[10][(size_t)NOUT * KPAD];   // [n][k], transposed + k-padded
__device__ __nv_bfloat16 g_wlo[10][(size_t)NOUT * KPAD];

// ==================== split-bf16 HMMA GEMM, cp.async double-buffered ====================
// C[M,256] = A[M,K] @ W^T (W stored [256 n][256 k]) + bias
// 128x128 block tile (grid.y = 2 N-tiles), 8 warps (2m x 4n), BK=32, 2-stage pipeline.
#define BM 128
#define BN 128
#define BK 32
#define LDS_A 40                    // padded smem stride (bf16); rows 16B-aligned, LDS conflict-free
#define TSZ (BM * LDS_A)            // elems per tile buffer
#define STAGE_ELEMS (4 * TSZ)       // Ahi|Alo|Bhi|Blo per stage
#define GEMM_SMEM (2 * STAGE_ELEMS * 2)  // bytes (2 stages, bf16)

__device__ __forceinline__ uint32_t smem_u32(const void* p) {
    uint32_t a;
    asm("{ .reg .u64 t; cvta.to.shared.u64 t, %1; cvt.u32.u64 %0, t; }" : "=r"(a) : "l"(p));
    return a;
}
__device__ __forceinline__ void cpa16(uint32_t dst, const void* src, int szbytes) {
    asm volatile("cp.async.ca.shared.global [%0], [%1], 16, %2;"
                 :: "r"(dst), "l"(src), "r"(szbytes));
}
#define CP_COMMIT() asm volatile("cp.async.commit_group;" ::: "memory")
#define CP_WAIT(n)  asm volatile("cp.async.wait_group %0;" :: "n"(n) : "memory")

__device__ __forceinline__ void mma_bf16(float* c, const uint32_t* a, const uint32_t* b) {
    asm volatile(
        "mma.sync.aligned.m16n8k16.row.col.f32.bf16.bf16.f32 "
        "{%0,%1,%2,%3}, {%4,%5,%6,%7}, {%8,%9}, {%0,%1,%2,%3};"
        : "+f"(c[0]), "+f"(c[1]), "+f"(c[2]), "+f"(c[3])
        : "r"(a[0]), "r"(a[1]), "r"(a[2]), "r"(a[3]), "r"(b[0]), "r"(b[1]));
}

__global__ __launch_bounds__(256) void gemm_split(
    const __nv_bfloat16* __restrict__ Ahi, const __nv_bfloat16* __restrict__ Alo,
    const __nv_bfloat16* __restrict__ Bhi, const __nv_bfloat16* __restrict__ Blo,
    const float* __restrict__ bias, float* __restrict__ C, int M, int K)
{
    extern __shared__ __nv_bfloat16 smem[];

    const int tid  = threadIdx.x;
    const int wid  = tid >> 5;
    const int lane = tid & 31;
    const int m0   = blockIdx.x * BM;
    const int n0   = blockIdx.y * BN;

    const int wm = (wid & 1) * 64;
    const int wn = (wid >> 1) * 32;
    const int gr  = lane >> 2;
    const int tig = lane & 3;

    // loader mapping: 128 rows x 32 cols bf16 per tile, 2 uint4 per thread per array
    const int r0  = tid >> 1;
    const int cg0 = (tid & 1) * 8;
    const int gmA = m0 + r0;
    const int aok = (gmA < M) ? 16 : 0;
    const size_t arow = (size_t)(aok ? gmA : 0) * KPAD;
    const size_t brow = (size_t)(n0 + r0) * KPAD;

    const int nk = K / BK;

    float acc[4][4][4];
#pragma unroll
    for (int i = 0; i < 4; i++)
#pragma unroll
        for (int j = 0; j < 4; j++)
#pragma unroll
            for (int r = 0; r < 4; r++) acc[i][j][r] = 0.f;

    // stage smem bases (element offsets)
    uint32_t sbase = smem_u32(smem);
    // issue loads for one stage
    auto load_stage = [&](int st, int kc) {
        uint32_t b = sbase + (uint32_t)(st * STAGE_ELEMS) * 2;
        uint32_t dA = b + (uint32_t)(r0 * LDS_A) * 2;
        uint32_t off0 = (uint32_t)cg0 * 2;
        uint32_t off1 = (uint32_t)(cg0 + 16) * 2;
#pragma unroll
        for (int half = 0; half < 2; half++) {
            int col = cg0 + half * 16;
            uint32_t doff = (half ? off1 : off0);
            cpa16(dA + doff,                    Ahi + arow + kc + col, aok);
            cpa16(dA + doff + (uint32_t)TSZ*2,  Alo + arow + kc + col, aok);
            cpa16(dA + doff + (uint32_t)TSZ*4,  Bhi + brow + kc + col, 16);
            cpa16(dA + doff + (uint32_t)TSZ*6,  Blo + brow + kc + col, 16);
        }
        CP_COMMIT();
    };

    load_stage(0, 0);

    for (int ki = 0; ki < nk; ki++) {
        if (ki + 1 < nk) {
            load_stage((ki + 1) & 1, (ki + 1) * BK);
            CP_WAIT(1);
        } else {
            CP_WAIT(0);
        }
        __syncthreads();

        const __nv_bfloat16* sAhi = smem + (ki & 1) * STAGE_ELEMS;
        const __nv_bfloat16* sAlo = sAhi + TSZ;
        const __nv_bfloat16* sBhi = sAhi + 2 * TSZ;
        const __nv_bfloat16* sBlo = sAhi + 3 * TSZ;

#pragma unroll
        for (int ks = 0; ks < BK; ks += 16) {
            uint32_t ah[4][4], al[4][4];
#pragma unroll
            for (int mt = 0; mt < 4; mt++) {
                int mr = wm + mt * 16;
                int c = ks + tig * 2;
                ah[mt][0] = *(const uint32_t*)(sAhi + (mr + gr)     * LDS_A + c);
                ah[mt][1] = *(const uint32_t*)(sAhi + (mr + gr + 8) * LDS_A + c);
                ah[mt][2] = *(const uint32_t*)(sAhi + (mr + gr)     * LDS_A + c + 8);
                ah[mt][3] = *(const uint32_t*)(sAhi + (mr + gr + 8) * LDS_A + c + 8);
                al[mt][0] = *(const uint32_t*)(sAlo + (mr + gr)     * LDS_A + c);
                al[mt][1] = *(const uint32_t*)(sAlo + (mr + gr + 8) * LDS_A + c);
                al[mt][2] = *(const uint32_t*)(sAlo + (mr + gr)     * LDS_A + c + 8);
                al[mt][3] = *(const uint32_t*)(sAlo + (mr + gr + 8) * LDS_A + c + 8);
            }
            uint32_t bh[4][2], bl[4][2];
#pragma unroll
            for (int nt = 0; nt < 4; nt++) {
                int nr = wn + nt * 8 + gr;
                int c = ks + tig * 2;
                bh[nt][0] = *(const uint32_t*)(sBhi + nr * LDS_A + c);
                bh[nt][1] = *(const uint32_t*)(sBhi + nr * LDS_A + c + 8);
                bl[nt][0] = *(const uint32_t*)(sBlo + nr * LDS_A + c);
                bl[nt][1] = *(const uint32_t*)(sBlo + nr * LDS_A + c + 8);
            }
#pragma unroll
            for (int mt = 0; mt < 4; mt++)
#pragma unroll
                for (int nt = 0; nt < 4; nt++) {
                    mma_bf16(acc[mt][nt], ah[mt], bh[nt]);
                    mma_bf16(acc[mt][nt], ah[mt], bl[nt]);
                    mma_bf16(acc[mt][nt], al[mt], bh[nt]);
                }
        }
        __syncthreads();
    }

    // ---- epilogue: direct global stores (float2 per frag-row) + bias ----
#pragma unroll
    for (int nt = 0; nt < 4; nt++) {
        int gc = n0 + wn + nt * 8 + tig * 2;
        float2 b2 = bias ? *(const float2*)(bias + gc) : make_float2(0.f, 0.f);
#pragma unroll
        for (int mt = 0; mt < 4; mt++) {
            int gm = m0 + wm + mt * 16 + gr;
            if (gm < M) {
                float2 v0 = make_float2(acc[mt][nt][0] + b2.x, acc[mt][nt][1] + b2.y);
                *(float2*)(C + (size_t)gm * NOUT + gc) = v0;
            }
            if (gm + 8 < M) {
                float2 v1 = make_float2(acc[mt][nt][2] + b2.x, acc[mt][nt][3] + b2.y);
                *(float2*)(C + (size_t)(gm + 8) * NOUT + gc) = v1;
            }
        }
    }
}

// ==================== conversion kernels ====================
__global__ void split_feat(const float* __restrict__ X,
                           __nv_bfloat16* __restrict__ hi, __nv_bfloat16* __restrict__ lo,
                           int M, int Kin, int do_relu)
{
    int idx = blockIdx.x * blockDim.x + threadIdx.x;
    if (idx >= M * KPAD) return;
    int k = idx & (KPAD - 1);
    float v = 0.f;
    if (k < Kin) v = X[(size_t)(idx >> 8) * Kin + k];
    if (do_relu) v = fmaxf(v, 0.f);
    __nv_bfloat16 h = __float2bfloat16(v);
    hi[idx] = h;
    lo[idx] = __float2bfloat16(v - __bfloat162float(h));
}

__global__ void split_weight(const float* __restrict__ W,
                             __nv_bfloat16* __restrict__ hi, __nv_bfloat16* __restrict__ lo,
                             int Kin)
{
    int idx = blockIdx.x * blockDim.x + threadIdx.x;
    if (idx >= NOUT * KPAD) return;
    int n = idx & 255, k = idx >> 8;
    float v = (k < Kin) ? W[(size_t)k * NOUT + n] : 0.f;
    __nv_bfloat16 h = __float2bfloat16(v);
    hi[(size_t)n * KPAD + k] = h;
    lo[(size_t)n * KPAD + k] = __float2bfloat16(v - __bfloat162float(h));
}

// ==================== edge attention ====================
__device__ __forceinline__ int enc_f(float f) {
    int i = __float_as_int(f);
    return (i >= 0) ? i : (i ^ 0x7fffffff);
}
__device__ __forceinline__ float dec_f(int e) {
    int raw = (e >= 0) ? e : (e ^ 0x7fffffff);
    return __int_as_float(raw);
}

__global__ void init_seg(int* __restrict__ m, float* __restrict__ den, int n) {
    int i = blockIdx.x * blockDim.x + threadIdx.x;
    if (i < n) { m[i] = 0x80000000; den[i] = 0.f; }
}

__global__ void edge_logits(const float* __restrict__ q, const float* __restrict__ k,
                            const float* __restrict__ eemb,
                            const int* __restrict__ src, const int* __restrict__ dst,
                            float* __restrict__ logit, int* __restrict__ mmax)
{
    int idx = blockIdx.x * blockDim.x + threadIdx.x;
    if (idx >= EE * HH) return;
    int e = idx >> 2, h = idx & 3;
    int s = src[e], d = dst[e];
    const float4* qp = (const float4*)(q    + (size_t)d * DNODE + h * CC);
    const float4* kp = (const float4*)(k    + (size_t)s * DNODE + h * CC);
    const float4* ep = (const float4*)(eemb + (size_t)e * DNODE + h * CC);
    float acc = 0.f;
#pragma unroll
    for (int i = 0; i < 16; i++) {
        float4 a = qp[i], b = kp[i], c = ep[i];
        acc += a.x * (b.x + c.x) + a.y * (b.y + c.y)
             + a.z * (b.z + c.z) + a.w * (b.w + c.w);
    }
    float lg = acc * 0.125f;
    logit[idx] = lg;
    atomicMax(&mmax[d * HH + h], enc_f(lg));
}

__global__ void edge_exp(const int* __restrict__ dst,
                         float* __restrict__ logit,
                         const int* __restrict__ mmax,
                         float* __restrict__ den)
{
    int idx = blockIdx.x * blockDim.x + threadIdx.x;
    if (idx >= EE * HH) return;
    int e = idx >> 2, h = idx & 3;
    int d = dst[e];
    float m = dec_f(mmax[d * HH + h]);
    float ex = __expf(logit[idx] - m);
    logit[idx] = ex;
    atomicAdd(&den[d * HH + h], ex);
}

__global__ void edge_agg(const float* __restrict__ v, const float* __restrict__ eemb,
                         const int* __restrict__ src, const int* __restrict__ dst,
                         const float* __restrict__ exv, const float* __restrict__ den,
                         float* __restrict__ agg)
{
    int idx = blockIdx.x * blockDim.x + threadIdx.x;
    if (idx >= EE * 64) return;
    int c4 = idx & 15;
    int h  = (idx >> 4) & 3;
    int e  = idx >> 6;
    int s = src[e], d = dst[e];
    float a = exv[e * HH + h] / (den[d * HH + h] + 1e-16f);
    int off = h * CC + c4 * 4;
    float4 vv = *(const float4*)(v    + (size_t)s * DNODE + off);
    float4 ev = *(const float4*)(eemb + (size_t)e * DNODE + off);
    float4 r = make_float4((vv.x + ev.x) * a, (vv.y + ev.y) * a,
                           (vv.z + ev.z) * a, (vv.w + ev.w) * a);
    float* addr = agg + (size_t)d * DNODE + off;
    asm volatile("red.global.add.v4.f32 [%0], {%1, %2, %3, %4};"
                 :: "l"(addr), "f"(r.x), "f"(r.y), "f"(r.z), "f"(r.w) : "memory");
}

// ==================== host side ====================
#define KEDGE 224   // 194 rounded up to BK multiple; cols 194..223 are zero-padded

static void run_layer(const __nv_bfloat16* ahi, const __nv_bfloat16* alo,
                      const __nv_bfloat16* ehi, const __nv_bfloat16* elo,
                      const __nv_bfloat16* whi, const __nv_bfloat16* wlo, size_t wstride,
                      const float* bq, const float* bk, const float* bv, const float* bs,
                      const int* src, const int* dst,
                      float* q, float* k, float* v, float* e,
                      float* ex, int* m, float* den, float* agg)
{
    dim3 gn((NN + BM - 1) / BM, NOUT / BN);
    dim3 ge((EE + BM - 1) / BM, NOUT / BN);
    gemm_split<<<gn, 256, GEMM_SMEM>>>(ahi, alo, whi + 0 * wstride, wlo + 0 * wstride, bq, q,   NN, KPAD);
    gemm_split<<<gn, 256, GEMM_SMEM>>>(ahi, alo, whi + 1 * wstride, wlo + 1 * wstride, bk, k,   NN, KPAD);
    gemm_split<<<gn, 256, GEMM_SMEM>>>(ahi, alo, whi + 2 * wstride, wlo + 2 * wstride, bv, v,   NN, KPAD);
    gemm_split<<<ge, 256, GEMM_SMEM>>>(ehi, elo, whi + 3 * wstride, wlo + 3 * wstride, nullptr, e, EE, KEDGE);
    gemm_split<<<gn, 256, GEMM_SMEM>>>(ahi, alo, whi + 4 * wstride, wlo + 4 * wstride, bs, agg, NN, KPAD);

    init_seg<<<(NN * HH + 255) / 256, 256>>>(m, den, NN * HH);
    edge_logits<<<(EE * HH + 255) / 256, 256>>>(q, k, e, src, dst, ex, m);
    edge_exp<<<(EE * HH + 255) / 256, 256>>>(dst, ex, m, den);
    edge_agg<<<(EE * 64 + 255) / 256, 256>>>(v, e, src, dst, ex, den, agg);
}

extern "C" void kernel_launch(void* const* d_in, const int* in_sizes, int n_in,
                              void* d_out, int out_size)
{
    const float* x   = (const float*)d_in[0];
    const int*   ei  = (const int*)  d_in[1];
    const float* ea  = (const float*)d_in[2];
    const float* W1[5] = { (const float*)d_in[3],  (const float*)d_in[5],
                           (const float*)d_in[7],  (const float*)d_in[9],
                           (const float*)d_in[10] };
    const float* b1[4] = { (const float*)d_in[4],  (const float*)d_in[6],
                           (const float*)d_in[8],  (const float*)d_in[11] };
    const float* W2[5] = { (const float*)d_in[12], (const float*)d_in[14],
                           (const float*)d_in[16], (const float*)d_in[18],
                           (const float*)d_in[19] };
    const float* b2[4] = { (const float*)d_in[13], (const float*)d_in[15],
                           (const float*)d_in[17], (const float*)d_in[20] };
    const int Kin[5] = { DNODE, DNODE, DNODE, EDD, DNODE };

    const int* src = ei;
    const int* dst = ei + EE;
    float* out = (float*)d_out;

    float *q, *k, *v, *x1, *e, *ex, *den;
    int* m;
    __nv_bfloat16 *ahi, *alo, *ehi, *elo, *whi, *wlo;
    cudaGetSymbolAddress((void**)&q,   g_q);
    cudaGetSymbolAddress((void**)&k,   g_k);
    cudaGetSymbolAddress((void**)&v,   g_v);
    cudaGetSymbolAddress((void**)&x1,  g_x1);
    cudaGetSymbolAddress((void**)&e,   g_e);
    cudaGetSymbolAddress((void**)&ex,  g_ex);
    cudaGetSymbolAddress((void**)&m,   g_m);
    cudaGetSymbolAddress((void**)&den, g_den);
    cudaGetSymbolAddress((void**)&ahi, g_ahi);
    cudaGetSymbolAddress((void**)&alo, g_alo);
    cudaGetSymbolAddress((void**)&ehi, g_ehi);
    cudaGetSymbolAddress((void**)&elo, g_elo);
    cudaGetSymbolAddress((void**)&whi, g_whi);
    cudaGetSymbolAddress((void**)&wlo, g_wlo);
    const size_t WS = (size_t)NOUT * KPAD;

    cudaFuncSetAttribute(gemm_split, cudaFuncAttributeMaxDynamicSharedMemorySize, GEMM_SMEM);

    for (int i = 0; i < 5; i++) {
        split_weight<<<(NOUT * KPAD + 255) / 256, 256>>>(W1[i], whi + i * WS,       wlo + i * WS,       Kin[i]);
        split_weight<<<(NOUT * KPAD + 255) / 256, 256>>>(W2[i], whi + (5 + i) * WS, wlo + (5 + i) * WS, Kin[i]);
    }
    split_feat<<<((size_t)EE * KPAD + 255) / 256, 256>>>(ea, ehi, elo, EE, EDD, 0);
    split_feat<<<((size_t)NN * KPAD + 255) / 256, 256>>>(x,  ahi, alo, NN, DNODE, 0);

    // ---- layer 1 ----
    run_layer(ahi, alo, ehi, elo, whi, wlo, WS,
              b1[0], b1[1], b1[2], b1[3], src, dst,
              q, k, v, e, ex, m, den, x1);

    // relu + re-split x1 as layer-2 input
    split_feat<<<((size_t)NN * KPAD + 255) / 256, 256>>>(x1, ahi, alo, NN, DNODE, 1);

    // ---- layer 2 ----
    run_layer(ahi, alo, ehi, elo, whi + 5 * WS, wlo + 5 * WS, WS,
              b2[0], b2[1], b2[2], b2[3], src, dst,
              q, k, v, e, ex, m, den, out);
}

// round 7
// speedup vs baseline: 1.7086x; 1.1504x over previous
#include <cuda_runtime.h>
#include <cuda_bf16.h>
#include <cstdint>

#define NN 50000
#define EE 250000
#define HH 4
#define CC 64
#define DNODE 256
#define EDD 194
#define KPAD 256
#define NOUT 256

// ---------------- scratch (device globals; no runtime allocation) ----------------
__device__ float g_q [(size_t)NN * DNODE];
__device__ float g_k [(size_t)NN * DNODE];
__device__ float g_v [(size_t)NN * DNODE];
__device__ float g_x1[(size_t)NN * DNODE];
__device__ float g_e [(size_t)EE * DNODE];
__device__ float g_ex[(size_t)EE * HH];
__device__ int   g_m [(size_t)NN * HH];
__device__ float g_den[(size_t)NN * HH];

// split-bf16 operand buffers
__device__ __nv_bfloat16 g_ahi[(size_t)NN * KPAD];
__device__ __nv_bfloat16 g_alo[(size_t)NN * KPAD];
__device__ __nv_bfloat16 g_ehi[(size_t)EE * KPAD];
__device__ __nv_bfloat16 g_elo[(size_t)EE * KPAD];
// per layer: [Wq|Wk|Wv|Ws] concatenated (4*256 rows) then We (256 rows); 2 layers
__device__ __nv_bfloat16 g_whi[10][(size_t)NOUT * KPAD];
__device__ __nv_bfloat16 g_wlo[10][(size_t)NOUT * KPAD];
__device__ float g_bias[2][4 * NOUT];   // packed bq|bk|bv|bs per layer

// ==================== split-bf16 HMMA GEMM, cp.async + ldmatrix ====================
#define BM 128
#define BN 128
#define BK 32
#define LDS_A 40
#define TSZ (BM * LDS_A)
#define STAGE_ELEMS (4 * TSZ)
#define GEMM_SMEM (2 * STAGE_ELEMS * 2)

__device__ __forceinline__ uint32_t smem_u32(const void* p) {
    uint32_t a;
    asm("{ .reg .u64 t; cvta.to.shared.u64 t, %1; cvt.u32.u64 %0, t; }" : "=r"(a) : "l"(p));
    return a;
}
__device__ __forceinline__ void cpa16(uint32_t dst, const void* src, int szbytes) {
    asm volatile("cp.async.ca.shared.global [%0], [%1], 16, %2;"
                 :: "r"(dst), "l"(src), "r"(szbytes));
}
#define CP_COMMIT() asm volatile("cp.async.commit_group;" ::: "memory")
#define CP_WAIT(n)  asm volatile("cp.async.wait_group %0;" :: "n"(n) : "memory")

__device__ __forceinline__ void ldsm4(uint32_t* r, uint32_t a) {
    asm volatile("ldmatrix.sync.aligned.m8n8.x4.shared.b16 {%0,%1,%2,%3}, [%4];"
                 : "=r"(r[0]), "=r"(r[1]), "=r"(r[2]), "=r"(r[3]) : "r"(a));
}
__device__ __forceinline__ void mma_bf16(float* c, const uint32_t* a, const uint32_t* b) {
    asm volatile(
        "mma.sync.aligned.m16n8k16.row.col.f32.bf16.bf16.f32 "
        "{%0,%1,%2,%3}, {%4,%5,%6,%7}, {%8,%9}, {%0,%1,%2,%3};"
        : "+f"(c[0]), "+f"(c[1]), "+f"(c[2]), "+f"(c[3])
        : "r"(a[0]), "r"(a[1]), "r"(a[2]), "r"(a[3]), "r"(b[0]), "r"(b[1]));
}

// C outputs: blockIdx.y selects 128-col tile of the concatenated [*,4*256] output;
// ob = blockIdx.y>>1 picks buffer (C0..C3), (blockIdx.y&1)*128 is the col offset.
__global__ __launch_bounds__(256) void gemm_split(
    const __nv_bfloat16* __restrict__ Ahi, const __nv_bfloat16* __restrict__ Alo,
    const __nv_bfloat16* __restrict__ Bhi, const __nv_bfloat16* __restrict__ Blo,
    const float* __restrict__ bias,
    float* __restrict__ C0, float* __restrict__ C1,
    float* __restrict__ C2, float* __restrict__ C3,
    int M, int K)
{
    extern __shared__ __nv_bfloat16 smem[];

    const int tid  = threadIdx.x;
    const int wid  = tid >> 5;
    const int lane = tid & 31;
    const int m0   = blockIdx.x * BM;

    const int ob = blockIdx.y >> 1;
    float* C = (ob == 0) ? C0 : (ob == 1) ? C1 : (ob == 2) ? C2 : C3;
    const int n0l = (blockIdx.y & 1) * BN;          // col offset within output buffer
    const int nglob0 = blockIdx.y * BN;             // row offset into concatenated B

    const int wm = (wid & 1) * 64;
    const int wn = (wid >> 1) * 32;
    const int gr  = lane >> 2;
    const int tig = lane & 3;

    // loader mapping
    const int r0  = tid >> 1;
    const int cg0 = (tid & 1) * 8;
    const int gmA = m0 + r0;
    const int aok = (gmA < M) ? 16 : 0;
    const size_t arow = (size_t)(aok ? gmA : 0) * KPAD;
    const size_t brow = (size_t)(nglob0 + r0) * KPAD;

    const int nk = K / BK;

    float acc[4][4][4];
#pragma unroll
    for (int i = 0; i < 4; i++)
#pragma unroll
        for (int j = 0; j < 4; j++)
#pragma unroll
            for (int r = 0; r < 4; r++) acc[i][j][r] = 0.f;

    uint32_t sbase = smem_u32(smem);

    auto load_stage = [&](int st, int kc) {
        uint32_t b = sbase + (uint32_t)(st * STAGE_ELEMS) * 2;
        uint32_t dA = b + (uint32_t)(r0 * LDS_A) * 2;
#pragma unroll
        for (int half = 0; half < 2; half++) {
            int col = cg0 + half * 16;
            uint32_t doff = (uint32_t)col * 2;
            cpa16(dA + doff,                    Ahi + arow + kc + col, aok);
            cpa16(dA + doff + (uint32_t)TSZ*2,  Alo + arow + kc + col, aok);
            cpa16(dA + doff + (uint32_t)TSZ*4,  Bhi + brow + kc + col, 16);
            cpa16(dA + doff + (uint32_t)TSZ*6,  Blo + brow + kc + col, 16);
        }
        CP_COMMIT();
    };

    // ldmatrix per-lane offsets (bytes, relative to tile base)
    const int aRow = lane & 15;
    const int aCol = (lane >> 4) * 8;                 // 0 or 8
    const uint32_t aOff = (uint32_t)((wm + aRow) * LDS_A + aCol) * 2;
    const int bRow = wn + (lane & 7) + ((lane >> 4) << 3);
    const int bCol = ((lane >> 3) & 1) * 8;
    const uint32_t bOff = (uint32_t)(bRow * LDS_A + bCol) * 2;

    load_stage(0, 0);

    for (int ki = 0; ki < nk; ki++) {
        if (ki + 1 < nk) {
            load_stage((ki + 1) & 1, (ki + 1) * BK);
            CP_WAIT(1);
        } else {
            CP_WAIT(0);
        }
        __syncthreads();

        uint32_t stb = sbase + (uint32_t)((ki & 1) * STAGE_ELEMS) * 2;
        uint32_t aHiB = stb, aLoB = stb + TSZ * 2;
        uint32_t bHiB = stb + TSZ * 4, bLoB = stb + TSZ * 6;

#pragma unroll
        for (int ks = 0; ks < BK; ks += 16) {
            uint32_t ah[4][4], al[4][4];
#pragma unroll
            for (int mt = 0; mt < 4; mt++) {
                uint32_t o = aOff + (uint32_t)(mt * 16 * LDS_A + ks) * 2;
                ldsm4(ah[mt], aHiB + o);
                ldsm4(al[mt], aLoB + o);
            }
            uint32_t bhf[8], blf[8];
#pragma unroll
            for (int p = 0; p < 2; p++) {
                uint32_t o = bOff + (uint32_t)(p * 16 * LDS_A + ks) * 2;
                ldsm4(bhf + 4 * p, bHiB + o);
                ldsm4(blf + 4 * p, bLoB + o);
            }
#pragma unroll
            for (int mt = 0; mt < 4; mt++)
#pragma unroll
                for (int nt = 0; nt < 4; nt++) {
                    mma_bf16(acc[mt][nt], ah[mt], bhf + nt * 2);
                    mma_bf16(acc[mt][nt], ah[mt], blf + nt * 2);
                    mma_bf16(acc[mt][nt], al[mt], bhf + nt * 2);
                }
        }
        __syncthreads();
    }

    // ---- epilogue ----
#pragma unroll
    for (int nt = 0; nt < 4; nt++) {
        int lc = wn + nt * 8 + tig * 2;                 // 0..127 within tile
        float2 b2 = bias ? *(const float2*)(bias + nglob0 + lc) : make_float2(0.f, 0.f);
        int gc = n0l + lc;
#pragma unroll
        for (int mt = 0; mt < 4; mt++) {
            int gm = m0 + wm + mt * 16 + gr;
            if (gm < M) {
                float2 v0 = make_float2(acc[mt][nt][0] + b2.x, acc[mt][nt][1] + b2.y);
                *(float2*)(C + (size_t)gm * NOUT + gc) = v0;
            }
            if (gm + 8 < M) {
                float2 v1 = make_float2(acc[mt][nt][2] + b2.x, acc[mt][nt][3] + b2.y);
                *(float2*)(C + (size_t)(gm + 8) * NOUT + gc) = v1;
            }
        }
    }
}

// ==================== conversion kernels ====================
__global__ void split_feat(const float* __restrict__ X,
                           __nv_bfloat16* __restrict__ hi, __nv_bfloat16* __restrict__ lo,
                           int M, int Kin, int do_relu)
{
    int idx = blockIdx.x * blockDim.x + threadIdx.x;
    if (idx >= M * KPAD) return;
    int k = idx & (KPAD - 1);
    float v = 0.f;
    if (k < Kin) v = X[(size_t)(idx >> 8) * Kin + k];
    if (do_relu) v = fmaxf(v, 0.f);
    __nv_bfloat16 h = __float2bfloat16(v);
    hi[idx] = h;
    lo[idx] = __float2bfloat16(v - __bfloat162float(h));
}

__global__ void split_weight(const float* __restrict__ W,
                             __nv_bfloat16* __restrict__ hi, __nv_bfloat16* __restrict__ lo,
                             int Kin)
{
    int idx = blockIdx.x * blockDim.x + threadIdx.x;
    if (idx >= NOUT * KPAD) return;
    int n = idx & 255, k = idx >> 8;
    float v = (k < Kin) ? W[(size_t)k * NOUT + n] : 0.f;
    __nv_bfloat16 h = __float2bfloat16(v);
    hi[(size_t)n * KPAD + k] = h;
    lo[(size_t)n * KPAD + k] = __float2bfloat16(v - __bfloat162float(h));
}

__global__ void pack_bias(const float* __restrict__ bq, const float* __restrict__ bk,
                          const float* __restrict__ bv, const float* __restrict__ bs,
                          float* __restrict__ out)
{
    int i = blockIdx.x * blockDim.x + threadIdx.x;
    if (i >= 4 * NOUT) return;
    const float* src = (i < 256) ? bq : (i < 512) ? bk : (i < 768) ? bv : bs;
    out[i] = src[i & 255];
}

// ==================== edge attention ====================
__device__ __forceinline__ int enc_f(float f) {
    int i = __float_as_int(f);
    return (i >= 0) ? i : (i ^ 0x7fffffff);
}
__device__ __forceinline__ float dec_f(int e) {
    int raw = (e >= 0) ? e : (e ^ 0x7fffffff);
    return __int_as_float(raw);
}

__global__ void init_seg(int* __restrict__ m, float* __restrict__ den, int n) {
    int i = blockIdx.x * blockDim.x + threadIdx.x;
    if (i < n) { m[i] = 0x80000000; den[i] = 0.f; }
}

__global__ void edge_logits(const float* __restrict__ q, const float* __restrict__ k,
                            const float* __restrict__ eemb,
                            const int* __restrict__ src, const int* __restrict__ dst,
                            float* __restrict__ logit, int* __restrict__ mmax)
{
    int idx = blockIdx.x * blockDim.x + threadIdx.x;
    if (idx >= EE * HH) return;
    int e = idx >> 2, h = idx & 3;
    int s = src[e], d = dst[e];
    const float4* qp = (const float4*)(q    + (size_t)d * DNODE + h * CC);
    const float4* kp = (const float4*)(k    + (size_t)s * DNODE + h * CC);
    const float4* ep = (const float4*)(eemb + (size_t)e * DNODE + h * CC);
    float acc = 0.f;
#pragma unroll
    for (int i = 0; i < 16; i++) {
        float4 a = qp[i], b = kp[i], c = ep[i];
        acc += a.x * (b.x + c.x) + a.y * (b.y + c.y)
             + a.z * (b.z + c.z) + a.w * (b.w + c.w);
    }
    float lg = acc * 0.125f;
    logit[idx] = lg;
    atomicMax(&mmax[d * HH + h], enc_f(lg));
}

__global__ void edge_exp(const int* __restrict__ dst,
                         float* __restrict__ logit,
                         const int* __restrict__ mmax,
                         float* __restrict__ den)
{
    int idx = blockIdx.x * blockDim.x + threadIdx.x;
    if (idx >= EE * HH) return;
    int e = idx >> 2, h = idx & 3;
    int d = dst[e];
    float m = dec_f(mmax[d * HH + h]);
    float ex = __expf(logit[idx] - m);
    logit[idx] = ex;
    atomicAdd(&den[d * HH + h], ex);
}

__global__ void edge_agg(const float* __restrict__ v, const float* __restrict__ eemb,
                         const int* __restrict__ src, const int* __restrict__ dst,
                         const float* __restrict__ exv, const float* __restrict__ den,
                         float* __restrict__ agg)
{
    int idx = blockIdx.x * blockDim.x + threadIdx.x;
    if (idx >= EE * 64) return;
    int c4 = idx & 15;
    int h  = (idx >> 4) & 3;
    int e  = idx >> 6;
    int s = src[e], d = dst[e];
    float a = exv[e * HH + h] / (den[d * HH + h] + 1e-16f);
    int off = h * CC + c4 * 4;
    float4 vv = *(const float4*)(v    + (size_t)s * DNODE + off);
    float4 ev = *(const float4*)(eemb + (size_t)e * DNODE + off);
    float4 r = make_float4((vv.x + ev.x) * a, (vv.y + ev.y) * a,
                           (vv.z + ev.z) * a, (vv.w + ev.w) * a);
    float* addr = agg + (size_t)d * DNODE + off;
    asm volatile("red.global.add.v4.f32 [%0], {%1, %2, %3, %4};"
                 :: "l"(addr), "f"(r.x), "f"(r.y), "f"(r.z), "f"(r.w) : "memory");
}

// ==================== host side ====================
#define KEDGE 224

static void run_layer(const __nv_bfloat16* ahi, const __nv_bfloat16* alo,
                      const __nv_bfloat16* ehi, const __nv_bfloat16* elo,
                      const __nv_bfloat16* whi, const __nv_bfloat16* wlo, size_t wstride,
                      const float* bias_packed,
                      const int* src, const int* dst,
                      float* q, float* k, float* v, float* e,
                      float* ex, int* m, float* den, float* agg)
{
    dim3 gn((NN + BM - 1) / BM, 8);      // merged Q|K|V|S node GEMM (N=1024)
    dim3 ge((EE + BM - 1) / BM, 2);      // edge GEMM (N=256)
    gemm_split<<<gn, 256, GEMM_SMEM>>>(ahi, alo, whi, wlo, bias_packed,
                                       q, k, v, agg, NN, KPAD);
    gemm_split<<<ge, 256, GEMM_SMEM>>>(ehi, elo, whi + 4 * wstride, wlo + 4 * wstride,
                                       nullptr, e, e, e, e, EE, KEDGE);

    init_seg<<<(NN * HH + 255) / 256, 256>>>(m, den, NN * HH);
    edge_logits<<<(EE * HH + 255) / 256, 256>>>(q, k, e, src, dst, ex, m);
    edge_exp<<<(EE * HH + 255) / 256, 256>>>(dst, ex, m, den);
    edge_agg<<<(EE * 64 + 255) / 256, 256>>>(v, e, src, dst, ex, den, agg);
}

extern "C" void kernel_launch(void* const* d_in, const int* in_sizes, int n_in,
                              void* d_out, int out_size)
{
    const float* x   = (const float*)d_in[0];
    const int*   ei  = (const int*)  d_in[1];
    const float* ea  = (const float*)d_in[2];
    // per layer, order in weight buffer: Wq, Wk, Wv, Ws, We
    const float* W1[5] = { (const float*)d_in[3],  (const float*)d_in[5],
                           (const float*)d_in[7],  (const float*)d_in[10],
                           (const float*)d_in[9] };
    const float* W2[5] = { (const float*)d_in[12], (const float*)d_in[14],
                           (const float*)d_in[16], (const float*)d_in[19],
                           (const float*)d_in[18] };
    const int Kin[5] = { DNODE, DNODE, DNODE, DNODE, EDD };

    const int* src = ei;
    const int* dst = ei + EE;
    float* out = (float*)d_out;

    float *q, *k, *v, *x1, *e, *ex, *den, *bias;
    int* m;
    __nv_bfloat16 *ahi, *alo, *ehi, *elo, *whi, *wlo;
    cudaGetSymbolAddress((void**)&q,    g_q);
    cudaGetSymbolAddress((void**)&k,    g_k);
    cudaGetSymbolAddress((void**)&v,    g_v);
    cudaGetSymbolAddress((void**)&x1,   g_x1);
    cudaGetSymbolAddress((void**)&e,    g_e);
    cudaGetSymbolAddress((void**)&ex,   g_ex);
    cudaGetSymbolAddress((void**)&m,    g_m);
    cudaGetSymbolAddress((void**)&den,  g_den);
    cudaGetSymbolAddress((void**)&ahi,  g_ahi);
    cudaGetSymbolAddress((void**)&alo,  g_alo);
    cudaGetSymbolAddress((void**)&ehi,  g_ehi);
    cudaGetSymbolAddress((void**)&elo,  g_elo);
    cudaGetSymbolAddress((void**)&whi,  g_whi);
    cudaGetSymbolAddress((void**)&wlo,  g_wlo);
    cudaGetSymbolAddress((void**)&bias, g_bias);
    const size_t WS = (size_t)NOUT * KPAD;

    cudaFuncSetAttribute(gemm_split, cudaFuncAttributeMaxDynamicSharedMemorySize, GEMM_SMEM);

    for (int i = 0; i < 5; i++) {
        split_weight<<<(NOUT * KPAD + 255) / 256, 256>>>(W1[i], whi + i * WS,       wlo + i * WS,       Kin[i]);
        split_weight<<<(NOUT * KPAD + 255) / 256, 256>>>(W2[i], whi + (5 + i) * WS, wlo + (5 + i) * WS, Kin[i]);
    }
    pack_bias<<<4, 256>>>((const float*)d_in[4],  (const float*)d_in[6],
                          (const float*)d_in[8],  (const float*)d_in[11], bias);
    pack_bias<<<4, 256>>>((const float*)d_in[13], (const float*)d_in[15],
                          (const float*)d_in[17], (const float*)d_in[20], bias + 4 * NOUT);

    split_feat<<<((size_t)EE * KPAD + 255) / 256, 256>>>(ea, ehi, elo, EE, EDD, 0);
    split_feat<<<((size_t)NN * KPAD + 255) / 256, 256>>>(x,  ahi, alo, NN, DNODE, 0);

    // ---- layer 1 ----
    run_layer(ahi, alo, ehi, elo, whi, wlo, WS, bias, src, dst,
              q, k, v, e, ex, m, den, x1);

    // relu + re-split x1 as layer-2 input
    split_feat<<<((size_t)NN * KPAD + 255) / 256, 256>>>(x1, ahi, alo, NN, DNODE, 1);

    // ---- layer 2 ----
    run_layer(ahi, alo, ehi, elo, whi + 5 * WS, wlo + 5 * WS, WS, bias + 4 * NOUT, src, dst,
              q, k, v, e, ex, m, den, out);
}

// round 8
// speedup vs baseline: 1.7185x; 1.0058x over previous
#include <cuda_runtime.h>
#include <cuda_bf16.h>
#include <cstdint>

#define NN 50000
#define EE 250000
#define HH 4
#define CC 64
#define DNODE 256
#define EDD 194
#define KPAD 256
#define NOUT 256

// ---------------- scratch (device globals; no runtime allocation) ----------------
__device__ float g_q [(size_t)NN * DNODE];
__device__ float g_k [(size_t)NN * DNODE];
__device__ float g_v [(size_t)NN * DNODE];
__device__ float g_x1[(size_t)NN * DNODE];
__device__ float g_e [(size_t)EE * DNODE];
__device__ float g_ex[(size_t)EE * HH];
__device__ int   g_m [(size_t)NN * HH];
__device__ float g_den[(size_t)NN * HH];

// split-bf16 operand buffers
__device__ __nv_bfloat16 g_ahi[(size_t)NN * KPAD];
__device__ __nv_bfloat16 g_alo[(size_t)NN * KPAD];
__device__ __nv_bfloat16 g_ehi[(size_t)EE * KPAD];
__device__ __nv_bfloat16 g_elo[(size_t)EE * KPAD];
// per layer: [Wq|Wk|Wv|Ws] concatenated (4*256 rows) then We (256 rows); 2 layers
__device__ __nv_bfloat16 g_whi[10][(size_t)NOUT * KPAD];
__device__ __nv_bfloat16 g_wlo[10][(size_t)NOUT * KPAD];
__device__ float g_bias[2][4 * NOUT];

// ==================== split-bf16 HMMA GEMM: 512 thr, 3-stage cp.async, ldmatrix ====================
#define BM 128
#define BN 128
#define BK 32
#define NTHR 512
#define NSTAGE 3
#define LDS_A 40
#define TSZ (BM * LDS_A)
#define STAGE_ELEMS (4 * TSZ)
#define GEMM_SMEM (NSTAGE * STAGE_ELEMS * 2)

__device__ __forceinline__ uint32_t smem_u32(const void* p) {
    uint32_t a;
    asm("{ .reg .u64 t; cvta.to.shared.u64 t, %1; cvt.u32.u64 %0, t; }" : "=r"(a) : "l"(p));
    return a;
}
__device__ __forceinline__ void cpa16(uint32_t dst, const void* src, int szbytes) {
    asm volatile("cp.async.ca.shared.global [%0], [%1], 16, %2;"
                 :: "r"(dst), "l"(src), "r"(szbytes));
}
#define CP_COMMIT() asm volatile("cp.async.commit_group;" ::: "memory")
#define CP_WAIT(n)  asm volatile("cp.async.wait_group %0;" :: "n"(n) : "memory")

__device__ __forceinline__ void ldsm4(uint32_t* r, uint32_t a) {
    asm volatile("ldmatrix.sync.aligned.m8n8.x4.shared.b16 {%0,%1,%2,%3}, [%4];"
                 : "=r"(r[0]), "=r"(r[1]), "=r"(r[2]), "=r"(r[3]) : "r"(a));
}
__device__ __forceinline__ void mma_bf16(float* c, const uint32_t* a, const uint32_t* b) {
    asm volatile(
        "mma.sync.aligned.m16n8k16.row.col.f32.bf16.bf16.f32 "
        "{%0,%1,%2,%3}, {%4,%5,%6,%7}, {%8,%9}, {%0,%1,%2,%3};"
        : "+f"(c[0]), "+f"(c[1]), "+f"(c[2]), "+f"(c[3])
        : "r"(a[0]), "r"(a[1]), "r"(a[2]), "r"(a[3]), "r"(b[0]), "r"(b[1]));
}

// blockIdx.y selects a 128-col tile of the concatenated [*, 4*256] output.
__global__ __launch_bounds__(NTHR) void gemm_split(
    const __nv_bfloat16* __restrict__ Ahi, const __nv_bfloat16* __restrict__ Alo,
    const __nv_bfloat16* __restrict__ Bhi, const __nv_bfloat16* __restrict__ Blo,
    const float* __restrict__ bias,
    float* __restrict__ C0, float* __restrict__ C1,
    float* __restrict__ C2, float* __restrict__ C3,
    int M, int K)
{
    extern __shared__ __nv_bfloat16 smem[];

    const int tid  = threadIdx.x;
    const int wid  = tid >> 5;
    const int lane = tid & 31;
    const int m0   = blockIdx.x * BM;

    const int ob = blockIdx.y >> 1;
    float* C = (ob == 0) ? C0 : (ob == 1) ? C1 : (ob == 2) ? C2 : C3;
    const int n0l = (blockIdx.y & 1) * BN;
    const int nglob0 = blockIdx.y * BN;

    // 16 warps: 4 m x 4 n, 32x32 warp tiles
    const int wm = (wid & 3) * 32;
    const int wn = (wid >> 2) * 32;
    const int gr  = lane >> 2;
    const int tig = lane & 3;

    // loader mapping: 512 threads, 1 uint4 per thread per tile
    const int r0  = tid >> 2;
    const int cg0 = (tid & 3) * 8;
    const int gmA = m0 + r0;
    const int aok = (gmA < M) ? 16 : 0;
    const size_t arow = (size_t)(aok ? gmA : 0) * KPAD;
    const size_t brow = (size_t)(nglob0 + r0) * KPAD;

    const int nk = K / BK;

    float acc[2][4][4];
#pragma unroll
    for (int i = 0; i < 2; i++)
#pragma unroll
        for (int j = 0; j < 4; j++)
#pragma unroll
            for (int r = 0; r < 4; r++) acc[i][j][r] = 0.f;

    uint32_t sbase = smem_u32(smem);

    auto load_stage = [&](int st, int kc) {
        uint32_t b = sbase + (uint32_t)(st * STAGE_ELEMS) * 2;
        uint32_t d = b + (uint32_t)(r0 * LDS_A + cg0) * 2;
        cpa16(d,                    Ahi + arow + kc + cg0, aok);
        cpa16(d + (uint32_t)TSZ*2,  Alo + arow + kc + cg0, aok);
        cpa16(d + (uint32_t)TSZ*4,  Bhi + brow + kc + cg0, 16);
        cpa16(d + (uint32_t)TSZ*6,  Blo + brow + kc + cg0, 16);
        CP_COMMIT();
    };

    // ldmatrix per-lane offsets (bytes, relative to tile base)
    const int aRow = lane & 15;
    const int aCol = (lane >> 4) * 8;
    const uint32_t aOff = (uint32_t)((wm + aRow) * LDS_A + aCol) * 2;
    const int bRow = wn + (lane & 7) + ((lane >> 4) << 3);
    const int bCol = ((lane >> 3) & 1) * 8;
    const uint32_t bOff = (uint32_t)(bRow * LDS_A + bCol) * 2;

    load_stage(0, 0);
    if (nk > 1) load_stage(1, BK);

    for (int ki = 0; ki < nk; ki++) {
        if (ki + 2 < nk) {
            load_stage((ki + 2) % NSTAGE, (ki + 2) * BK);
            CP_WAIT(2);
        } else if (ki + 1 < nk) {
            CP_WAIT(1);
        } else {
            CP_WAIT(0);
        }
        __syncthreads();

        uint32_t stb = sbase + (uint32_t)((ki % NSTAGE) * STAGE_ELEMS) * 2;
        uint32_t aHiB = stb, aLoB = stb + TSZ * 2;
        uint32_t bHiB = stb + TSZ * 4, bLoB = stb + TSZ * 6;

#pragma unroll
        for (int ks = 0; ks < BK; ks += 16) {
            uint32_t ah[2][4], al[2][4];
#pragma unroll
            for (int mt = 0; mt < 2; mt++) {
                uint32_t o = aOff + (uint32_t)(mt * 16 * LDS_A + ks) * 2;
                ldsm4(ah[mt], aHiB + o);
                ldsm4(al[mt], aLoB + o);
            }
            uint32_t bhf[8], blf[8];
#pragma unroll
            for (int p = 0; p < 2; p++) {
                uint32_t o = bOff + (uint32_t)(p * 16 * LDS_A + ks) * 2;
                ldsm4(bhf + 4 * p, bHiB + o);
                ldsm4(blf + 4 * p, bLoB + o);
            }
#pragma unroll
            for (int mt = 0; mt < 2; mt++)
#pragma unroll
                for (int nt = 0; nt < 4; nt++) {
                    mma_bf16(acc[mt][nt], ah[mt], bhf + nt * 2);
                    mma_bf16(acc[mt][nt], ah[mt], blf + nt * 2);
                    mma_bf16(acc[mt][nt], al[mt], bhf + nt * 2);
                }
        }
        __syncthreads();
    }

    // ---- epilogue ----
#pragma unroll
    for (int nt = 0; nt < 4; nt++) {
        int lc = wn + nt * 8 + tig * 2;
        float2 b2 = bias ? *(const float2*)(bias + nglob0 + lc) : make_float2(0.f, 0.f);
        int gc = n0l + lc;
#pragma unroll
        for (int mt = 0; mt < 2; mt++) {
            int gm = m0 + wm + mt * 16 + gr;
            if (gm < M) {
                float2 v0 = make_float2(acc[mt][nt][0] + b2.x, acc[mt][nt][1] + b2.y);
                *(float2*)(C + (size_t)gm * NOUT + gc) = v0;
            }
            if (gm + 8 < M) {
                float2 v1 = make_float2(acc[mt][nt][2] + b2.x, acc[mt][nt][3] + b2.y);
                *(float2*)(C + (size_t)(gm + 8) * NOUT + gc) = v1;
            }
        }
    }
}

// ==================== conversion kernels ====================
__global__ void split_feat(const float* __restrict__ X,
                           __nv_bfloat16* __restrict__ hi, __nv_bfloat16* __restrict__ lo,
                           int M, int Kin, int do_relu)
{
    int idx = blockIdx.x * blockDim.x + threadIdx.x;
    if (idx >= M * KPAD) return;
    int k = idx & (KPAD - 1);
    float v = 0.f;
    if (k < Kin) v = X[(size_t)(idx >> 8) * Kin + k];
    if (do_relu) v = fmaxf(v, 0.f);
    __nv_bfloat16 h = __float2bfloat16(v);
    hi[idx] = h;
    lo[idx] = __float2bfloat16(v - __bfloat162float(h));
}

__global__ void split_weight(const float* __restrict__ W,
                             __nv_bfloat16* __restrict__ hi, __nv_bfloat16* __restrict__ lo,
                             int Kin)
{
    int idx = blockIdx.x * blockDim.x + threadIdx.x;
    if (idx >= NOUT * KPAD) return;
    int n = idx & 255, k = idx >> 8;
    float v = (k < Kin) ? W[(size_t)k * NOUT + n] : 0.f;
    __nv_bfloat16 h = __float2bfloat16(v);
    hi[(size_t)n * KPAD + k] = h;
    lo[(size_t)n * KPAD + k] = __float2bfloat16(v - __bfloat162float(h));
}

__global__ void pack_bias(const float* __restrict__ bq, const float* __restrict__ bk,
                          const float* __restrict__ bv, const float* __restrict__ bs,
                          float* __restrict__ out)
{
    int i = blockIdx.x * blockDim.x + threadIdx.x;
    if (i >= 4 * NOUT) return;
    const float* src = (i < 256) ? bq : (i < 512) ? bk : (i < 768) ? bv : bs;
    out[i] = src[i & 255];
}

// ==================== edge attention ====================
__device__ __forceinline__ int enc_f(float f) {
    int i = __float_as_int(f);
    return (i >= 0) ? i : (i ^ 0x7fffffff);
}
__device__ __forceinline__ float dec_f(int e) {
    int raw = (e >= 0) ? e : (e ^ 0x7fffffff);
    return __int_as_float(raw);
}

__global__ void init_seg(int* __restrict__ m, float* __restrict__ den, int n) {
    int i = blockIdx.x * blockDim.x + threadIdx.x;
    if (i < n) { m[i] = 0x80000000; den[i] = 0.f; }
}

__global__ void edge_logits(const float* __restrict__ q, const float* __restrict__ k,
                            const float* __restrict__ eemb,
                            const int* __restrict__ src, const int* __restrict__ dst,
                            float* __restrict__ logit, int* __restrict__ mmax)
{
    int idx = blockIdx.x * blockDim.x + threadIdx.x;
    if (idx >= EE * HH) return;
    int e = idx >> 2, h = idx & 3;
    int s = src[e], d = dst[e];
    const float4* qp = (const float4*)(q    + (size_t)d * DNODE + h * CC);
    const float4* kp = (const float4*)(k    + (size_t)s * DNODE + h * CC);
    const float4* ep = (const float4*)(eemb + (size_t)e * DNODE + h * CC);
    float acc = 0.f;
#pragma unroll
    for (int i = 0; i < 16; i++) {
        float4 a = qp[i], b = kp[i], c = ep[i];
        acc += a.x * (b.x + c.x) + a.y * (b.y + c.y)
             + a.z * (b.z + c.z) + a.w * (b.w + c.w);
    }
    float lg = acc * 0.125f;
    logit[idx] = lg;
    atomicMax(&mmax[d * HH + h], enc_f(lg));
}

__global__ void edge_exp(const int* __restrict__ dst,
                         float* __restrict__ logit,
                         const int* __restrict__ mmax,
                         float* __restrict__ den)
{
    int idx = blockIdx.x * blockDim.x + threadIdx.x;
    if (idx >= EE * HH) return;
    int e = idx >> 2, h = idx & 3;
    int d = dst[e];
    float m = dec_f(mmax[d * HH + h]);
    float ex = __expf(logit[idx] - m);
    logit[idx] = ex;
    atomicAdd(&den[d * HH + h], ex);
}

__global__ void edge_agg(const float* __restrict__ v, const float* __restrict__ eemb,
                         const int* __restrict__ src, const int* __restrict__ dst,
                         const float* __restrict__ exv, const float* __restrict__ den,
                         float* __restrict__ agg)
{
    int idx = blockIdx.x * blockDim.x + threadIdx.x;
    if (idx >= EE * 64) return;
    int c4 = idx & 15;
    int h  = (idx >> 4) & 3;
    int e  = idx >> 6;
    int s = src[e], d = dst[e];
    float a = exv[e * HH + h] / (den[d * HH + h] + 1e-16f);
    int off = h * CC + c4 * 4;
    float4 vv = *(const float4*)(v    + (size_t)s * DNODE + off);
    float4 ev = *(const float4*)(eemb + (size_t)e * DNODE + off);
    float4 r = make_float4((vv.x + ev.x) * a, (vv.y + ev.y) * a,
                           (vv.z + ev.z) * a, (vv.w + ev.w) * a);
    float* addr = agg + (size_t)d * DNODE + off;
    asm volatile("red.global.add.v4.f32 [%0], {%1, %2, %3, %4};"
                 :: "l"(addr), "f"(r.x), "f"(r.y), "f"(r.z), "f"(r.w) : "memory");
}

// ==================== host side ====================
#define KEDGE 224

static void run_layer(const __nv_bfloat16* ahi, const __nv_bfloat16* alo,
                      const __nv_bfloat16* ehi, const __nv_bfloat16* elo,
                      const __nv_bfloat16* whi, const __nv_bfloat16* wlo, size_t wstride,
                      const float* bias_packed,
                      const int* src, const int* dst,
                      float* q, float* k, float* v, float* e,
                      float* ex, int* m, float* den, float* agg)
{
    dim3 gn((NN + BM - 1) / BM, 8);
    dim3 ge((EE + BM - 1) / BM, 2);
    gemm_split<<<gn, NTHR, GEMM_SMEM>>>(ahi, alo, whi, wlo, bias_packed,
                                        q, k, v, agg, NN, KPAD);
    gemm_split<<<ge, NTHR, GEMM_SMEM>>>(ehi, elo, whi + 4 * wstride, wlo + 4 * wstride,
                                        nullptr, e, e, e, e, EE, KEDGE);

    init_seg<<<(NN * HH + 255) / 256, 256>>>(m, den, NN * HH);
    edge_logits<<<(EE * HH + 255) / 256, 256>>>(q, k, e, src, dst, ex, m);
    edge_exp<<<(EE * HH + 255) / 256, 256>>>(dst, ex, m, den);
    edge_agg<<<(EE * 64 + 255) / 256, 256>>>(v, e, src, dst, ex, den, agg);
}

extern "C" void kernel_launch(void* const* d_in, const int* in_sizes, int n_in,
                              void* d_out, int out_size)
{
    const float* x   = (const float*)d_in[0];
    const int*   ei  = (const int*)  d_in[1];
    const float* ea  = (const float*)d_in[2];
    // per layer, order in weight buffer: Wq, Wk, Wv, Ws, We
    const float* W1[5] = { (const float*)d_in[3],  (const float*)d_in[5],
                           (const float*)d_in[7],  (const float*)d_in[10],
                           (const float*)d_in[9] };
    const float* W2[5] = { (const float*)d_in[12], (const float*)d_in[14],
                           (const float*)d_in[16], (const float*)d_in[19],
                           (const float*)d_in[18] };
    const int Kin[5] = { DNODE, DNODE, DNODE, DNODE, EDD };

    const int* src = ei;
    const int* dst = ei + EE;
    float* out = (float*)d_out;

    float *q, *k, *v, *x1, *e, *ex, *den, *bias;
    int* m;
    __nv_bfloat16 *ahi, *alo, *ehi, *elo, *whi, *wlo;
    cudaGetSymbolAddress((void**)&q,    g_q);
    cudaGetSymbolAddress((void**)&k,    g_k);
    cudaGetSymbolAddress((void**)&v,    g_v);
    cudaGetSymbolAddress((void**)&x1,   g_x1);
    cudaGetSymbolAddress((void**)&e,    g_e);
    cudaGetSymbolAddress((void**)&ex,   g_ex);
    cudaGetSymbolAddress((void**)&m,    g_m);
    cudaGetSymbolAddress((void**)&den,  g_den);
    cudaGetSymbolAddress((void**)&ahi,  g_ahi);
    cudaGetSymbolAddress((void**)&alo,  g_alo);
    cudaGetSymbolAddress((void**)&ehi,  g_ehi);
    cudaGetSymbolAddress((void**)&elo,  g_elo);
    cudaGetSymbolAddress((void**)&whi,  g_whi);
    cudaGetSymbolAddress((void**)&wlo,  g_wlo);
    cudaGetSymbolAddress((void**)&bias, g_bias);
    const size_t WS = (size_t)NOUT * KPAD;

    cudaFuncSetAttribute(gemm_split, cudaFuncAttributeMaxDynamicSharedMemorySize, GEMM_SMEM);

    for (int i = 0; i < 5; i++) {
        split_weight<<<(NOUT * KPAD + 255) / 256, 256>>>(W1[i], whi + i * WS,       wlo + i * WS,       Kin[i]);
        split_weight<<<(NOUT * KPAD + 255) / 256, 256>>>(W2[i], whi + (5 + i) * WS, wlo + (5 + i) * WS, Kin[i]);
    }
    pack_bias<<<4, 256>>>((const float*)d_in[4],  (const float*)d_in[6],
                          (const float*)d_in[8],  (const float*)d_in[11], bias);
    pack_bias<<<4, 256>>>((const float*)d_in[13], (const float*)d_in[15],
                          (const float*)d_in[17], (const float*)d_in[20], bias + 4 * NOUT);

    split_feat<<<((size_t)EE * KPAD + 255) / 256, 256>>>(ea, ehi, elo, EE, EDD, 0);
    split_feat<<<((size_t)NN * KPAD + 255) / 256, 256>>>(x,  ahi, alo, NN, DNODE, 0);

    // ---- layer 1 ----
    run_layer(ahi, alo, ehi, elo, whi, wlo, WS, bias, src, dst,
              q, k, v, e, ex, m, den, x1);

    // relu + re-split x1 as layer-2 input
    split_feat<<<((size_t)NN * KPAD + 255) / 256, 256>>>(x1, ahi, alo, NN, DNODE, 1);

    // ---- layer 2 ----
    run_layer(ahi, alo, ehi, elo, whi + 5 * WS, wlo + 5 * WS, WS, bias + 4 * NOUT, src, dst,
              q, k, v, e, ex, m, den, out);
}

// round 9
// speedup vs baseline: 1.9417x; 1.1299x over previous
#include <cuda_runtime.h>
#include <cuda_bf16.h>
#include <cstdint>

#define NN 50000
#define EE 250000
#define HH 4
#define CC 64
#define DNODE 256
#define EDD 194
#define KPAD 256
#define NOUT 256

// ---------------- scratch (device globals; no runtime allocation) ----------------
__device__ float g_q   [(size_t)NN * DNODE];
__device__ float g_k   [(size_t)NN * DNODE];
__device__ float g_v   [(size_t)NN * DNODE];
__device__ float g_skip[(size_t)NN * DNODE];   // skip GEMM output
__device__ float g_agg [(size_t)NN * DNODE];   // unnormalized attention aggregate
__device__ float g_e   [(size_t)EE * DNODE];   // edge embeddings
__device__ float g_den [(size_t)NN * HH];      // segment sum of exp

// split-bf16 operand buffers
__device__ __nv_bfloat16 g_ahi[(size_t)NN * KPAD];
__device__ __nv_bfloat16 g_alo[(size_t)NN * KPAD];
__device__ __nv_bfloat16 g_ehi[(size_t)EE * KPAD];
__device__ __nv_bfloat16 g_elo[(size_t)EE * KPAD];
// per layer: [Wq|Wk|Wv|Ws] concatenated (4*256 rows) then We (256 rows); 2 layers
__device__ __nv_bfloat16 g_whi[10][(size_t)NOUT * KPAD];
__device__ __nv_bfloat16 g_wlo[10][(size_t)NOUT * KPAD];
__device__ float g_bias[2][4 * NOUT];

// ==================== split-bf16 HMMA GEMM: 512 thr, 3-stage cp.async, ldmatrix ====================
#define BM 128
#define BN 128
#define BK 32
#define NTHR 512
#define NSTAGE 3
#define LDS_A 40
#define TSZ (BM * LDS_A)
#define STAGE_ELEMS (4 * TSZ)
#define GEMM_SMEM (NSTAGE * STAGE_ELEMS * 2)

__device__ __forceinline__ uint32_t smem_u32(const void* p) {
    uint32_t a;
    asm("{ .reg .u64 t; cvta.to.shared.u64 t, %1; cvt.u32.u64 %0, t; }" : "=r"(a) : "l"(p));
    return a;
}
__device__ __forceinline__ void cpa16(uint32_t dst, const void* src, int szbytes) {
    asm volatile("cp.async.ca.shared.global [%0], [%1], 16, %2;"
                 :: "r"(dst), "l"(src), "r"(szbytes));
}
#define CP_COMMIT() asm volatile("cp.async.commit_group;" ::: "memory")
#define CP_WAIT(n)  asm volatile("cp.async.wait_group %0;" :: "n"(n) : "memory")

__device__ __forceinline__ void ldsm4(uint32_t* r, uint32_t a) {
    asm volatile("ldmatrix.sync.aligned.m8n8.x4.shared.b16 {%0,%1,%2,%3}, [%4];"
                 : "=r"(r[0]), "=r"(r[1]), "=r"(r[2]), "=r"(r[3]) : "r"(a));
}
__device__ __forceinline__ void mma_bf16(float* c, const uint32_t* a, const uint32_t* b) {
    asm volatile(
        "mma.sync.aligned.m16n8k16.row.col.f32.bf16.bf16.f32 "
        "{%0,%1,%2,%3}, {%4,%5,%6,%7}, {%8,%9}, {%0,%1,%2,%3};"
        : "+f"(c[0]), "+f"(c[1]), "+f"(c[2]), "+f"(c[3])
        : "r"(a[0]), "r"(a[1]), "r"(a[2]), "r"(a[3]), "r"(b[0]), "r"(b[1]));
}

__global__ __launch_bounds__(NTHR) void gemm_split(
    const __nv_bfloat16* __restrict__ Ahi, const __nv_bfloat16* __restrict__ Alo,
    const __nv_bfloat16* __restrict__ Bhi, const __nv_bfloat16* __restrict__ Blo,
    const float* __restrict__ bias,
    float* __restrict__ C0, float* __restrict__ C1,
    float* __restrict__ C2, float* __restrict__ C3,
    int M, int K)
{
    extern __shared__ __nv_bfloat16 smem[];

    const int tid  = threadIdx.x;
    const int wid  = tid >> 5;
    const int lane = tid & 31;
    const int m0   = blockIdx.x * BM;

    const int ob = blockIdx.y >> 1;
    float* C = (ob == 0) ? C0 : (ob == 1) ? C1 : (ob == 2) ? C2 : C3;
    const int n0l = (blockIdx.y & 1) * BN;
    const int nglob0 = blockIdx.y * BN;

    const int wm = (wid & 3) * 32;
    const int wn = (wid >> 2) * 32;
    const int gr  = lane >> 2;
    const int tig = lane & 3;

    const int r0  = tid >> 2;
    const int cg0 = (tid & 3) * 8;
    const int gmA = m0 + r0;
    const int aok = (gmA < M) ? 16 : 0;
    const size_t arow = (size_t)(aok ? gmA : 0) * KPAD;
    const size_t brow = (size_t)(nglob0 + r0) * KPAD;

    const int nk = K / BK;

    float acc[2][4][4];
#pragma unroll
    for (int i = 0; i < 2; i++)
#pragma unroll
        for (int j = 0; j < 4; j++)
#pragma unroll
            for (int r = 0; r < 4; r++) acc[i][j][r] = 0.f;

    uint32_t sbase = smem_u32(smem);

    auto load_stage = [&](int st, int kc) {
        uint32_t b = sbase + (uint32_t)(st * STAGE_ELEMS) * 2;
        uint32_t d = b + (uint32_t)(r0 * LDS_A + cg0) * 2;
        cpa16(d,                    Ahi + arow + kc + cg0, aok);
        cpa16(d + (uint32_t)TSZ*2,  Alo + arow + kc + cg0, aok);
        cpa16(d + (uint32_t)TSZ*4,  Bhi + brow + kc + cg0, 16);
        cpa16(d + (uint32_t)TSZ*6,  Blo + brow + kc + cg0, 16);
        CP_COMMIT();
    };

    const int aRow = lane & 15;
    const int aCol = (lane >> 4) * 8;
    const uint32_t aOff = (uint32_t)((wm + aRow) * LDS_A + aCol) * 2;
    const int bRow = wn + (lane & 7) + ((lane >> 4) << 3);
    const int bCol = ((lane >> 3) & 1) * 8;
    const uint32_t bOff = (uint32_t)(bRow * LDS_A + bCol) * 2;

    load_stage(0, 0);
    if (nk > 1) load_stage(1, BK);

    for (int ki = 0; ki < nk; ki++) {
        if (ki + 2 < nk) {
            load_stage((ki + 2) % NSTAGE, (ki + 2) * BK);
            CP_WAIT(2);
        } else if (ki + 1 < nk) {
            CP_WAIT(1);
        } else {
            CP_WAIT(0);
        }
        __syncthreads();

        uint32_t stb = sbase + (uint32_t)((ki % NSTAGE) * STAGE_ELEMS) * 2;
        uint32_t aHiB = stb, aLoB = stb + TSZ * 2;
        uint32_t bHiB = stb + TSZ * 4, bLoB = stb + TSZ * 6;

#pragma unroll
        for (int ks = 0; ks < BK; ks += 16) {
            uint32_t ah[2][4], al[2][4];
#pragma unroll
            for (int mt = 0; mt < 2; mt++) {
                uint32_t o = aOff + (uint32_t)(mt * 16 * LDS_A + ks) * 2;
                ldsm4(ah[mt], aHiB + o);
                ldsm4(al[mt], aLoB + o);
            }
            uint32_t bhf[8], blf[8];
#pragma unroll
            for (int p = 0; p < 2; p++) {
                uint32_t o = bOff + (uint32_t)(p * 16 * LDS_A + ks) * 2;
                ldsm4(bhf + 4 * p, bHiB + o);
                ldsm4(blf + 4 * p, bLoB + o);
            }
#pragma unroll
            for (int mt = 0; mt < 2; mt++)
#pragma unroll
                for (int nt = 0; nt < 4; nt++) {
                    mma_bf16(acc[mt][nt], ah[mt], bhf + nt * 2);
                    mma_bf16(acc[mt][nt], ah[mt], blf + nt * 2);
                    mma_bf16(acc[mt][nt], al[mt], bhf + nt * 2);
                }
        }
        __syncthreads();
    }

#pragma unroll
    for (int nt = 0; nt < 4; nt++) {
        int lc = wn + nt * 8 + tig * 2;
        float2 b2 = bias ? *(const float2*)(bias + nglob0 + lc) : make_float2(0.f, 0.f);
        int gc = n0l + lc;
#pragma unroll
        for (int mt = 0; mt < 2; mt++) {
            int gm = m0 + wm + mt * 16 + gr;
            if (gm < M) {
                float2 v0 = make_float2(acc[mt][nt][0] + b2.x, acc[mt][nt][1] + b2.y);
                *(float2*)(C + (size_t)gm * NOUT + gc) = v0;
            }
            if (gm + 8 < M) {
                float2 v1 = make_float2(acc[mt][nt][2] + b2.x, acc[mt][nt][3] + b2.y);
                *(float2*)(C + (size_t)(gm + 8) * NOUT + gc) = v1;
            }
        }
    }
}

// ==================== conversion kernels ====================
__global__ void split_feat(const float* __restrict__ X,
                           __nv_bfloat16* __restrict__ hi, __nv_bfloat16* __restrict__ lo,
                           int M, int Kin)
{
    int idx = blockIdx.x * blockDim.x + threadIdx.x;
    if (idx >= M * KPAD) return;
    int k = idx & (KPAD - 1);
    float v = 0.f;
    if (k < Kin) v = X[(size_t)(idx >> 8) * Kin + k];
    __nv_bfloat16 h = __float2bfloat16(v);
    hi[idx] = h;
    lo[idx] = __float2bfloat16(v - __bfloat162float(h));
}

__global__ void split_weight(const float* __restrict__ W,
                             __nv_bfloat16* __restrict__ hi, __nv_bfloat16* __restrict__ lo,
                             int Kin)
{
    int idx = blockIdx.x * blockDim.x + threadIdx.x;
    if (idx >= NOUT * KPAD) return;
    int n = idx & 255, k = idx >> 8;
    float v = (k < Kin) ? W[(size_t)k * NOUT + n] : 0.f;
    __nv_bfloat16 h = __float2bfloat16(v);
    hi[(size_t)n * KPAD + k] = h;
    lo[(size_t)n * KPAD + k] = __float2bfloat16(v - __bfloat162float(h));
}

__global__ void pack_bias(const float* __restrict__ bq, const float* __restrict__ bk,
                          const float* __restrict__ bv, const float* __restrict__ bs,
                          float* __restrict__ out)
{
    int i = blockIdx.x * blockDim.x + threadIdx.x;
    if (i >= 4 * NOUT) return;
    const float* src = (i < 256) ? bq : (i < 512) ? bk : (i < 768) ? bv : bs;
    out[i] = src[i & 255];
}

// ==================== fused edge attention ====================
// zero agg + den
__global__ void zero_agg(float* __restrict__ agg, float* __restrict__ den) {
    int i = blockIdx.x * blockDim.x + threadIdx.x;
    if (i < NN * 64) ((float4*)agg)[i] = make_float4(0.f, 0.f, 0.f, 0.f);
    if (i < NN) ((float4*)den)[i] = make_float4(0.f, 0.f, 0.f, 0.f);
}

// one warp per edge: logit -> exp -> scatter exp*(v[src]+e) and den
__global__ __launch_bounds__(256) void edge_fused(
    const float* __restrict__ q, const float* __restrict__ k,
    const float* __restrict__ eemb, const float* __restrict__ v,
    const int* __restrict__ src, const int* __restrict__ dst,
    float* __restrict__ den, float* __restrict__ agg)
{
    int warp = (blockIdx.x * blockDim.x + threadIdx.x) >> 5;
    if (warp >= EE) return;
    const int lane = threadIdx.x & 31;
    const int h = lane >> 3;
    const int part = lane & 7;
    const int s = src[warp];
    const int d = dst[warp];
    const int off = h * CC + part * 8;

    const float4* qp = (const float4*)(q    + (size_t)d * DNODE + off);
    const float4* kp = (const float4*)(k    + (size_t)s * DNODE + off);
    const float4* ep = (const float4*)(eemb + (size_t)warp * DNODE + off);

    float4 q0 = qp[0], q1 = qp[1];
    float4 k0 = kp[0], k1 = kp[1];
    float4 e0 = ep[0], e1 = ep[1];

    float dot = q0.x * (k0.x + e0.x) + q0.y * (k0.y + e0.y)
              + q0.z * (k0.z + e0.z) + q0.w * (k0.w + e0.w)
              + q1.x * (k1.x + e1.x) + q1.y * (k1.y + e1.y)
              + q1.z * (k1.z + e1.z) + q1.w * (k1.w + e1.w);
    dot += __shfl_xor_sync(0xffffffffu, dot, 1);
    dot += __shfl_xor_sync(0xffffffffu, dot, 2);
    dot += __shfl_xor_sync(0xffffffffu, dot, 4);

    float ex = __expf(dot * 0.125f);   // 1/sqrt(64); no max-shift (range-safe in fp32)
    if (part == 0) atomicAdd(&den[d * HH + h], ex);

    const float4* vp = (const float4*)(v + (size_t)s * DNODE + off);
    float4 v0 = vp[0], v1 = vp[1];
    float4 r0 = make_float4((v0.x + e0.x) * ex, (v0.y + e0.y) * ex,
                            (v0.z + e0.z) * ex, (v0.w + e0.w) * ex);
    float4 r1 = make_float4((v1.x + e1.x) * ex, (v1.y + e1.y) * ex,
                            (v1.z + e1.z) * ex, (v1.w + e1.w) * ex);
    float* a0 = agg + (size_t)d * DNODE + off;
    asm volatile("red.global.add.v4.f32 [%0], {%1, %2, %3, %4};"
                 :: "l"(a0), "f"(r0.x), "f"(r0.y), "f"(r0.z), "f"(r0.w) : "memory");
    asm volatile("red.global.add.v4.f32 [%0], {%1, %2, %3, %4};"
                 :: "l"(a0 + 4), "f"(r1.x), "f"(r1.y), "f"(r1.z), "f"(r1.w) : "memory");
}

// normalize + skip; mode 1: relu + write bf16 split (layer-2 input); mode 0: write f32 out
__global__ void normalize_out(const float* __restrict__ agg, const float* __restrict__ den,
                              const float* __restrict__ skip,
                              float* __restrict__ outf,
                              __nv_bfloat16* __restrict__ hi, __nv_bfloat16* __restrict__ lo,
                              int mode)
{
    int idx = blockIdx.x * blockDim.x + threadIdx.x;   // over NN*64 float4s
    if (idx >= NN * 64) return;
    int n = idx >> 6;
    int c4 = idx & 63;
    int h = c4 >> 4;
    float dd = den[n * HH + h] + 1e-16f;
    float inv = 1.0f / dd;
    float4 a = ((const float4*)agg)[idx];
    float4 s = ((const float4*)skip)[idx];
    float4 r = make_float4(a.x * inv + s.x, a.y * inv + s.y,
                           a.z * inv + s.z, a.w * inv + s.w);
    if (mode == 1) {
        r.x = fmaxf(r.x, 0.f); r.y = fmaxf(r.y, 0.f);
        r.z = fmaxf(r.z, 0.f); r.w = fmaxf(r.w, 0.f);
        __nv_bfloat16 h0 = __float2bfloat16(r.x), h1 = __float2bfloat16(r.y);
        __nv_bfloat16 h2 = __float2bfloat16(r.z), h3 = __float2bfloat16(r.w);
        __nv_bfloat16 l0 = __float2bfloat16(r.x - __bfloat162float(h0));
        __nv_bfloat16 l1 = __float2bfloat16(r.y - __bfloat162float(h1));
        __nv_bfloat16 l2 = __float2bfloat16(r.z - __bfloat162float(h2));
        __nv_bfloat16 l3 = __float2bfloat16(r.w - __bfloat162float(h3));
        ushort4 hv = make_ushort4(*(unsigned short*)&h0, *(unsigned short*)&h1,
                                  *(unsigned short*)&h2, *(unsigned short*)&h3);
        ushort4 lv = make_ushort4(*(unsigned short*)&l0, *(unsigned short*)&l1,
                                  *(unsigned short*)&l2, *(unsigned short*)&l3);
        *(ushort4*)(hi + (size_t)idx * 4) = hv;
        *(ushort4*)(lo + (size_t)idx * 4) = lv;
    } else {
        ((float4*)outf)[idx] = r;
    }
}

// ==================== host side ====================
#define KEDGE 224

static void run_layer(const __nv_bfloat16* ahi, const __nv_bfloat16* alo,
                      const __nv_bfloat16* ehi, const __nv_bfloat16* elo,
                      const __nv_bfloat16* whi, const __nv_bfloat16* wlo, size_t wstride,
                      const float* bias_packed,
                      const int* src, const int* dst,
                      float* q, float* k, float* v, float* e,
                      float* skip, float* agg, float* den,
                      float* outf, __nv_bfloat16* out_hi, __nv_bfloat16* out_lo, int mode)
{
    dim3 gn((NN + BM - 1) / BM, 8);
    dim3 ge((EE + BM - 1) / BM, 2);
    gemm_split<<<gn, NTHR, GEMM_SMEM>>>(ahi, alo, whi, wlo, bias_packed,
                                        q, k, v, skip, NN, KPAD);
    gemm_split<<<ge, NTHR, GEMM_SMEM>>>(ehi, elo, whi + 4 * wstride, wlo + 4 * wstride,
                                        nullptr, e, e, e, e, EE, KEDGE);

    zero_agg<<<(NN * 64 + 255) / 256, 256>>>(agg, den);
    edge_fused<<<(EE * 32 + 255) / 256, 256>>>(q, k, e, v, src, dst, den, agg);
    normalize_out<<<(NN * 64 + 255) / 256, 256>>>(agg, den, skip, outf, out_hi, out_lo, mode);
}

extern "C" void kernel_launch(void* const* d_in, const int* in_sizes, int n_in,
                              void* d_out, int out_size)
{
    const float* x   = (const float*)d_in[0];
    const int*   ei  = (const int*)  d_in[1];
    const float* ea  = (const float*)d_in[2];
    // per layer, order in weight buffer: Wq, Wk, Wv, Ws, We
    const float* W1[5] = { (const float*)d_in[3],  (const float*)d_in[5],
                           (const float*)d_in[7],  (const float*)d_in[10],
                           (const float*)d_in[9] };
    const float* W2[5] = { (const float*)d_in[12], (const float*)d_in[14],
                           (const float*)d_in[16], (const float*)d_in[19],
                           (const float*)d_in[18] };
    const int Kin[5] = { DNODE, DNODE, DNODE, DNODE, EDD };

    const int* src = ei;
    const int* dst = ei + EE;
    float* out = (float*)d_out;

    float *q, *k, *v, *skip, *agg, *e, *den, *bias;
    __nv_bfloat16 *ahi, *alo, *ehi, *elo, *whi, *wlo;
    cudaGetSymbolAddress((void**)&q,    g_q);
    cudaGetSymbolAddress((void**)&k,    g_k);
    cudaGetSymbolAddress((void**)&v,    g_v);
    cudaGetSymbolAddress((void**)&skip, g_skip);
    cudaGetSymbolAddress((void**)&agg,  g_agg);
    cudaGetSymbolAddress((void**)&e,    g_e);
    cudaGetSymbolAddress((void**)&den,  g_den);
    cudaGetSymbolAddress((void**)&ahi,  g_ahi);
    cudaGetSymbolAddress((void**)&alo,  g_alo);
    cudaGetSymbolAddress((void**)&ehi,  g_ehi);
    cudaGetSymbolAddress((void**)&elo,  g_elo);
    cudaGetSymbolAddress((void**)&whi,  g_whi);
    cudaGetSymbolAddress((void**)&wlo,  g_wlo);
    cudaGetSymbolAddress((void**)&bias, g_bias);
    const size_t WS = (size_t)NOUT * KPAD;

    cudaFuncSetAttribute(gemm_split, cudaFuncAttributeMaxDynamicSharedMemorySize, GEMM_SMEM);

    for (int i = 0; i < 5; i++) {
        split_weight<<<(NOUT * KPAD + 255) / 256, 256>>>(W1[i], whi + i * WS,       wlo + i * WS,       Kin[i]);
        split_weight<<<(NOUT * KPAD + 255) / 256, 256>>>(W2[i], whi + (5 + i) * WS, wlo + (5 + i) * WS, Kin[i]);
    }
    pack_bias<<<4, 256>>>((const float*)d_in[4],  (const float*)d_in[6],
                          (const float*)d_in[8],  (const float*)d_in[11], bias);
    pack_bias<<<4, 256>>>((const float*)d_in[13], (const float*)d_in[15],
                          (const float*)d_in[17], (const float*)d_in[20], bias + 4 * NOUT);

    split_feat<<<((size_t)EE * KPAD + 255) / 256, 256>>>(ea, ehi, elo, EE, EDD);
    split_feat<<<((size_t)NN * KPAD + 255) / 256, 256>>>(x,  ahi, alo, NN, DNODE);

    // ---- layer 1: normalize writes bf16 split of relu(out) directly ----
    run_layer(ahi, alo, ehi, elo, whi, wlo, WS, bias, src, dst,
              q, k, v, e, skip, agg, den, nullptr, ahi, alo, 1);

    // ---- layer 2: normalize writes d_out ----
    run_layer(ahi, alo, ehi, elo, whi + 5 * WS, wlo + 5 * WS, WS, bias + 4 * NOUT, src, dst,
              q, k, v, e, skip, agg, den, out, nullptr, nullptr, 0);
}

// round 10
// speedup vs baseline: 2.0028x; 1.0314x over previous
#include <cuda_runtime.h>
#include <cuda_bf16.h>
#include <cstdint>

#define NN 50000
#define EE 250000
#define HH 4
#define CC 64
#define DNODE 256
#define EDD 194
#define KPAD 256
#define NOUT 256

// ---------------- scratch (device globals; no runtime allocation) ----------------
__device__ float g_q   [(size_t)NN * DNODE];
__device__ float g_k   [(size_t)NN * DNODE];
__device__ float g_v   [(size_t)NN * DNODE];
__device__ float g_skip[(size_t)NN * DNODE];
__device__ float g_e   [(size_t)EE * DNODE];

// edge sort-by-dst (computed once per call; edge_index identical for both layers)
__device__ int g_cnt [NN];
__device__ int g_off [NN + 1];
__device__ int g_pos [NN];
__device__ int g_order[EE];

// split-bf16 operand buffers
__device__ __nv_bfloat16 g_ahi[(size_t)NN * KPAD];
__device__ __nv_bfloat16 g_alo[(size_t)NN * KPAD];
__device__ __nv_bfloat16 g_ehi[(size_t)EE * KPAD];
__device__ __nv_bfloat16 g_elo[(size_t)EE * KPAD];
// per layer: [Wq|Wk|Wv|Ws] concatenated (4*256 rows) then We (256 rows); 2 layers
__device__ __nv_bfloat16 g_whi[10][(size_t)NOUT * KPAD];
__device__ __nv_bfloat16 g_wlo[10][(size_t)NOUT * KPAD];
__device__ float g_bias[2][4 * NOUT];

// ==================== split-bf16 HMMA GEMM (validated R8) ====================
#define BM 128
#define BN 128
#define BK 32
#define NTHR 512
#define NSTAGE 3
#define LDS_A 40
#define TSZ (BM * LDS_A)
#define STAGE_ELEMS (4 * TSZ)
#define GEMM_SMEM (NSTAGE * STAGE_ELEMS * 2)

__device__ __forceinline__ uint32_t smem_u32(const void* p) {
    uint32_t a;
    asm("{ .reg .u64 t; cvta.to.shared.u64 t, %1; cvt.u32.u64 %0, t; }" : "=r"(a) : "l"(p));
    return a;
}
__device__ __forceinline__ void cpa16(uint32_t dst, const void* src, int szbytes) {
    asm volatile("cp.async.ca.shared.global [%0], [%1], 16, %2;"
                 :: "r"(dst), "l"(src), "r"(szbytes));
}
#define CP_COMMIT() asm volatile("cp.async.commit_group;" ::: "memory")
#define CP_WAIT(n)  asm volatile("cp.async.wait_group %0;" :: "n"(n) : "memory")

__device__ __forceinline__ void ldsm4(uint32_t* r, uint32_t a) {
    asm volatile("ldmatrix.sync.aligned.m8n8.x4.shared.b16 {%0,%1,%2,%3}, [%4];"
                 : "=r"(r[0]), "=r"(r[1]), "=r"(r[2]), "=r"(r[3]) : "r"(a));
}
__device__ __forceinline__ void mma_bf16(float* c, const uint32_t* a, const uint32_t* b) {
    asm volatile(
        "mma.sync.aligned.m16n8k16.row.col.f32.bf16.bf16.f32 "
        "{%0,%1,%2,%3}, {%4,%5,%6,%7}, {%8,%9}, {%0,%1,%2,%3};"
        : "+f"(c[0]), "+f"(c[1]), "+f"(c[2]), "+f"(c[3])
        : "r"(a[0]), "r"(a[1]), "r"(a[2]), "r"(a[3]), "r"(b[0]), "r"(b[1]));
}

__global__ __launch_bounds__(NTHR) void gemm_split(
    const __nv_bfloat16* __restrict__ Ahi, const __nv_bfloat16* __restrict__ Alo,
    const __nv_bfloat16* __restrict__ Bhi, const __nv_bfloat16* __restrict__ Blo,
    const float* __restrict__ bias,
    float* __restrict__ C0, float* __restrict__ C1,
    float* __restrict__ C2, float* __restrict__ C3,
    int M, int K)
{
    extern __shared__ __nv_bfloat16 smem[];

    const int tid  = threadIdx.x;
    const int wid  = tid >> 5;
    const int lane = tid & 31;
    const int m0   = blockIdx.x * BM;

    const int ob = blockIdx.y >> 1;
    float* C = (ob == 0) ? C0 : (ob == 1) ? C1 : (ob == 2) ? C2 : C3;
    const int n0l = (blockIdx.y & 1) * BN;
    const int nglob0 = blockIdx.y * BN;

    const int wm = (wid & 3) * 32;
    const int wn = (wid >> 2) * 32;
    const int gr  = lane >> 2;
    const int tig = lane & 3;

    const int r0  = tid >> 2;
    const int cg0 = (tid & 3) * 8;
    const int gmA = m0 + r0;
    const int aok = (gmA < M) ? 16 : 0;
    const size_t arow = (size_t)(aok ? gmA : 0) * KPAD;
    const size_t brow = (size_t)(nglob0 + r0) * KPAD;

    const int nk = K / BK;

    float acc[2][4][4];
#pragma unroll
    for (int i = 0; i < 2; i++)
#pragma unroll
        for (int j = 0; j < 4; j++)
#pragma unroll
            for (int r = 0; r < 4; r++) acc[i][j][r] = 0.f;

    uint32_t sbase = smem_u32(smem);

    auto load_stage = [&](int st, int kc) {
        uint32_t b = sbase + (uint32_t)(st * STAGE_ELEMS) * 2;
        uint32_t d = b + (uint32_t)(r0 * LDS_A + cg0) * 2;
        cpa16(d,                    Ahi + arow + kc + cg0, aok);
        cpa16(d + (uint32_t)TSZ*2,  Alo + arow + kc + cg0, aok);
        cpa16(d + (uint32_t)TSZ*4,  Bhi + brow + kc + cg0, 16);
        cpa16(d + (uint32_t)TSZ*6,  Blo + brow + kc + cg0, 16);
        CP_COMMIT();
    };

    const int aRow = lane & 15;
    const int aCol = (lane >> 4) * 8;
    const uint32_t aOff = (uint32_t)((wm + aRow) * LDS_A + aCol) * 2;
    const int bRow = wn + (lane & 7) + ((lane >> 4) << 3);
    const int bCol = ((lane >> 3) & 1) * 8;
    const uint32_t bOff = (uint32_t)(bRow * LDS_A + bCol) * 2;

    load_stage(0, 0);
    if (nk > 1) load_stage(1, BK);

    for (int ki = 0; ki < nk; ki++) {
        if (ki + 2 < nk) {
            load_stage((ki + 2) % NSTAGE, (ki + 2) * BK);
            CP_WAIT(2);
        } else if (ki + 1 < nk) {
            CP_WAIT(1);
        } else {
            CP_WAIT(0);
        }
        __syncthreads();

        uint32_t stb = sbase + (uint32_t)((ki % NSTAGE) * STAGE_ELEMS) * 2;
        uint32_t aHiB = stb, aLoB = stb + TSZ * 2;
        uint32_t bHiB = stb + TSZ * 4, bLoB = stb + TSZ * 6;

#pragma unroll
        for (int ks = 0; ks < BK; ks += 16) {
            uint32_t ah[2][4], al[2][4];
#pragma unroll
            for (int mt = 0; mt < 2; mt++) {
                uint32_t o = aOff + (uint32_t)(mt * 16 * LDS_A + ks) * 2;
                ldsm4(ah[mt], aHiB + o);
                ldsm4(al[mt], aLoB + o);
            }
            uint32_t bhf[8], blf[8];
#pragma unroll
            for (int p = 0; p < 2; p++) {
                uint32_t o = bOff + (uint32_t)(p * 16 * LDS_A + ks) * 2;
                ldsm4(bhf + 4 * p, bHiB + o);
                ldsm4(blf + 4 * p, bLoB + o);
            }
#pragma unroll
            for (int mt = 0; mt < 2; mt++)
#pragma unroll
                for (int nt = 0; nt < 4; nt++) {
                    mma_bf16(acc[mt][nt], ah[mt], bhf + nt * 2);
                    mma_bf16(acc[mt][nt], ah[mt], blf + nt * 2);
                    mma_bf16(acc[mt][nt], al[mt], bhf + nt * 2);
                }
        }
        __syncthreads();
    }

#pragma unroll
    for (int nt = 0; nt < 4; nt++) {
        int lc = wn + nt * 8 + tig * 2;
        float2 b2 = bias ? *(const float2*)(bias + nglob0 + lc) : make_float2(0.f, 0.f);
        int gc = n0l + lc;
#pragma unroll
        for (int mt = 0; mt < 2; mt++) {
            int gm = m0 + wm + mt * 16 + gr;
            if (gm < M) {
                float2 v0 = make_float2(acc[mt][nt][0] + b2.x, acc[mt][nt][1] + b2.y);
                *(float2*)(C + (size_t)gm * NOUT + gc) = v0;
            }
            if (gm + 8 < M) {
                float2 v1 = make_float2(acc[mt][nt][2] + b2.x, acc[mt][nt][3] + b2.y);
                *(float2*)(C + (size_t)(gm + 8) * NOUT + gc) = v1;
            }
        }
    }
}

// ==================== conversion kernels ====================
__global__ void split_feat(const float* __restrict__ X,
                           __nv_bfloat16* __restrict__ hi, __nv_bfloat16* __restrict__ lo,
                           int M, int Kin)
{
    int idx = blockIdx.x * blockDim.x + threadIdx.x;
    if (idx >= M * KPAD) return;
    int k = idx & (KPAD - 1);
    float v = 0.f;
    if (k < Kin) v = X[(size_t)(idx >> 8) * Kin + k];
    __nv_bfloat16 h = __float2bfloat16(v);
    hi[idx] = h;
    lo[idx] = __float2bfloat16(v - __bfloat162float(h));
}

__global__ void split_weight(const float* __restrict__ W,
                             __nv_bfloat16* __restrict__ hi, __nv_bfloat16* __restrict__ lo,
                             int Kin)
{
    int idx = blockIdx.x * blockDim.x + threadIdx.x;
    if (idx >= NOUT * KPAD) return;
    int n = idx & 255, k = idx >> 8;
    float v = (k < Kin) ? W[(size_t)k * NOUT + n] : 0.f;
    __nv_bfloat16 h = __float2bfloat16(v);
    hi[(size_t)n * KPAD + k] = h;
    lo[(size_t)n * KPAD + k] = __float2bfloat16(v - __bfloat162float(h));
}

__global__ void pack_bias(const float* __restrict__ bq, const float* __restrict__ bk,
                          const float* __restrict__ bv, const float* __restrict__ bs,
                          float* __restrict__ out)
{
    int i = blockIdx.x * blockDim.x + threadIdx.x;
    if (i >= 4 * NOUT) return;
    const float* src = (i < 256) ? bq : (i < 512) ? bk : (i < 768) ? bv : bs;
    out[i] = src[i & 255];
}

// ==================== edge sort-by-dst (once per call) ====================
__global__ void sort_hist(const int* __restrict__ dst, int* __restrict__ cnt) {
    int i = blockIdx.x * blockDim.x + threadIdx.x;
    if (i < NN) cnt[i] = 0;
    __syncthreads();   // no-op across grid; cnt zeroed by separate pass below
}
__global__ void zero_cnt(int* __restrict__ cnt) {
    int i = blockIdx.x * blockDim.x + threadIdx.x;
    if (i < NN) cnt[i] = 0;
}
__global__ void hist_dst(const int* __restrict__ dst, int* __restrict__ cnt) {
    int i = blockIdx.x * blockDim.x + threadIdx.x;
    if (i < EE) atomicAdd(&cnt[dst[i]], 1);
}
// single-block exclusive scan over NN counters
__global__ __launch_bounds__(1024) void scan_cnt(const int* __restrict__ cnt,
                                                 int* __restrict__ off, int* __restrict__ pos)
{
    __shared__ int ssum[1024];
    const int tid = threadIdx.x;
    const int PER = (NN + 1023) / 1024;   // 49
    const int base = tid * PER;
    int s = 0;
    for (int j = 0; j < PER; j++) {
        int i = base + j;
        if (i < NN) s += cnt[i];
    }
    ssum[tid] = s;
    __syncthreads();
    // Hillis-Steele inclusive scan
    for (int d = 1; d < 1024; d <<= 1) {
        int t = (tid >= d) ? ssum[tid - d] : 0;
        __syncthreads();
        ssum[tid] += t;
        __syncthreads();
    }
    int run = (tid > 0) ? ssum[tid - 1] : 0;
    for (int j = 0; j < PER; j++) {
        int i = base + j;
        if (i < NN) {
            off[i] = run;
            pos[i] = run;
            run += cnt[i];
        }
    }
    if (tid == 1023) off[NN] = run;
}
__global__ void scatter_edges(const int* __restrict__ dst, int* __restrict__ pos,
                              int* __restrict__ order)
{
    int i = blockIdx.x * blockDim.x + threadIdx.x;
    if (i >= EE) return;
    int p = atomicAdd(&pos[dst[i]], 1);
    order[p] = i;
}

// ==================== fused per-dst attention (softmax + agg + skip + out) ====================
// one warp per dst node; 8 floats per lane (h = lane>>3 head, part = lane&7)
__global__ __launch_bounds__(256) void edge_dst(
    const float* __restrict__ q, const float* __restrict__ k,
    const float* __restrict__ eemb, const float* __restrict__ v,
    const int* __restrict__ srcv, const int* __restrict__ off,
    const int* __restrict__ order, const float* __restrict__ skip,
    float* __restrict__ outf,
    __nv_bfloat16* __restrict__ hi, __nv_bfloat16* __restrict__ lo,
    int mode)
{
    int w = (blockIdx.x * blockDim.x + threadIdx.x) >> 5;
    if (w >= NN) return;
    const int lane = threadIdx.x & 31;
    const int h = lane >> 3;
    const int part = lane & 7;
    const int co = h * CC + part * 8;       // this lane's 8 channels

    const int start = off[w], end = off[w + 1];

    const float4* qp = (const float4*)(q + (size_t)w * DNODE + co);
    float4 q0 = qp[0], q1 = qp[1];

    float acc[8] = {0.f, 0.f, 0.f, 0.f, 0.f, 0.f, 0.f, 0.f};
    float den = 0.f;

    for (int i = start; i < end; i++) {
        int e = order[i];
        int s = srcv[e];
        const float4* kp = (const float4*)(k    + (size_t)s * DNODE + co);
        const float4* ep = (const float4*)(eemb + (size_t)e * DNODE + co);
        float4 k0 = kp[0], k1 = kp[1];
        float4 e0 = ep[0], e1 = ep[1];

        float dot = q0.x * (k0.x + e0.x) + q0.y * (k0.y + e0.y)
                  + q0.z * (k0.z + e0.z) + q0.w * (k0.w + e0.w)
                  + q1.x * (k1.x + e1.x) + q1.y * (k1.y + e1.y)
                  + q1.z * (k1.z + e1.z) + q1.w * (k1.w + e1.w);
        dot += __shfl_xor_sync(0xffffffffu, dot, 1);
        dot += __shfl_xor_sync(0xffffffffu, dot, 2);
        dot += __shfl_xor_sync(0xffffffffu, dot, 4);

        float ex = __expf(dot * 0.125f);    // 1/sqrt(64); range-safe in fp32
        den += ex;

        const float4* vp = (const float4*)(v + (size_t)s * DNODE + co);
        float4 v0 = vp[0], v1 = vp[1];
        acc[0] += ex * (v0.x + e0.x); acc[1] += ex * (v0.y + e0.y);
        acc[2] += ex * (v0.z + e0.z); acc[3] += ex * (v0.w + e0.w);
        acc[4] += ex * (v1.x + e1.x); acc[5] += ex * (v1.y + e1.y);
        acc[6] += ex * (v1.z + e1.z); acc[7] += ex * (v1.w + e1.w);
    }

    float inv = 1.0f / (den + 1e-16f);
    const float4* sp = (const float4*)(skip + (size_t)w * DNODE + co);
    float4 s0 = sp[0], s1 = sp[1];
    float r[8];
    r[0] = acc[0] * inv + s0.x; r[1] = acc[1] * inv + s0.y;
    r[2] = acc[2] * inv + s0.z; r[3] = acc[3] * inv + s0.w;
    r[4] = acc[4] * inv + s1.x; r[5] = acc[5] * inv + s1.y;
    r[6] = acc[6] * inv + s1.z; r[7] = acc[7] * inv + s1.w;

    if (mode == 1) {
        ushort4 hv[2], lv[2];
#pragma unroll
        for (int g = 0; g < 2; g++) {
#pragma unroll
            for (int j = 0; j < 4; j++) {
                float x = fmaxf(r[g * 4 + j], 0.f);
                __nv_bfloat16 hb = __float2bfloat16(x);
                __nv_bfloat16 lb = __float2bfloat16(x - __bfloat162float(hb));
                ((unsigned short*)&hv[g])[j] = *(unsigned short*)&hb;
                ((unsigned short*)&lv[g])[j] = *(unsigned short*)&lb;
            }
        }
        size_t base = (size_t)w * KPAD + co;
        *(ushort4*)(hi + base)     = hv[0];
        *(ushort4*)(lo + base)     = lv[0];
        *(ushort4*)(hi + base + 4) = hv[1];
        *(ushort4*)(lo + base + 4) = lv[1];
    } else {
        float4* op = (float4*)(outf + (size_t)w * DNODE + co);
        op[0] = make_float4(r[0], r[1], r[2], r[3]);
        op[1] = make_float4(r[4], r[5], r[6], r[7]);
    }
}

// ==================== host side ====================
#define KEDGE 224

static void run_layer(const __nv_bfloat16* ahi, const __nv_bfloat16* alo,
                      const __nv_bfloat16* ehi, const __nv_bfloat16* elo,
                      const __nv_bfloat16* whi, const __nv_bfloat16* wlo, size_t wstride,
                      const float* bias_packed,
                      const int* src, const int* off, const int* order,
                      float* q, float* k, float* v, float* e, float* skip,
                      float* outf, __nv_bfloat16* out_hi, __nv_bfloat16* out_lo, int mode)
{
    dim3 gn((NN + BM - 1) / BM, 8);
    dim3 ge((EE + BM - 1) / BM, 2);
    gemm_split<<<gn, NTHR, GEMM_SMEM>>>(ahi, alo, whi, wlo, bias_packed,
                                        q, k, v, skip, NN, KPAD);
    gemm_split<<<ge, NTHR, GEMM_SMEM>>>(ehi, elo, whi + 4 * wstride, wlo + 4 * wstride,
                                        nullptr, e, e, e, e, EE, KEDGE);

    edge_dst<<<(NN * 32 + 255) / 256, 256>>>(q, k, e, v, src, off, order, skip,
                                             outf, out_hi, out_lo, mode);
}

extern "C" void kernel_launch(void* const* d_in, const int* in_sizes, int n_in,
                              void* d_out, int out_size)
{
    const float* x   = (const float*)d_in[0];
    const int*   ei  = (const int*)  d_in[1];
    const float* ea  = (const float*)d_in[2];
    // per layer, order in weight buffer: Wq, Wk, Wv, Ws, We
    const float* W1[5] = { (const float*)d_in[3],  (const float*)d_in[5],
                           (const float*)d_in[7],  (const float*)d_in[10],
                           (const float*)d_in[9] };
    const float* W2[5] = { (const float*)d_in[12], (const float*)d_in[14],
                           (const float*)d_in[16], (const float*)d_in[19],
                           (const float*)d_in[18] };
    const int Kin[5] = { DNODE, DNODE, DNODE, DNODE, EDD };

    const int* src = ei;
    const int* dst = ei + EE;
    float* out = (float*)d_out;

    float *q, *k, *v, *skip, *e, *bias;
    int *cnt, *off, *pos, *order;
    __nv_bfloat16 *ahi, *alo, *ehi, *elo, *whi, *wlo;
    cudaGetSymbolAddress((void**)&q,     g_q);
    cudaGetSymbolAddress((void**)&k,     g_k);
    cudaGetSymbolAddress((void**)&v,     g_v);
    cudaGetSymbolAddress((void**)&skip,  g_skip);
    cudaGetSymbolAddress((void**)&e,     g_e);
    cudaGetSymbolAddress((void**)&cnt,   g_cnt);
    cudaGetSymbolAddress((void**)&off,   g_off);
    cudaGetSymbolAddress((void**)&pos,   g_pos);
    cudaGetSymbolAddress((void**)&order, g_order);
    cudaGetSymbolAddress((void**)&ahi,   g_ahi);
    cudaGetSymbolAddress((void**)&alo,   g_alo);
    cudaGetSymbolAddress((void**)&ehi,   g_ehi);
    cudaGetSymbolAddress((void**)&elo,   g_elo);
    cudaGetSymbolAddress((void**)&whi,   g_whi);
    cudaGetSymbolAddress((void**)&wlo,   g_wlo);
    cudaGetSymbolAddress((void**)&bias,  g_bias);
    const size_t WS = (size_t)NOUT * KPAD;

    cudaFuncSetAttribute(gemm_split, cudaFuncAttributeMaxDynamicSharedMemorySize, GEMM_SMEM);

    // ---- edge sort by dst (once; shared by both layers) ----
    zero_cnt<<<(NN + 255) / 256, 256>>>(cnt);
    hist_dst<<<(EE + 255) / 256, 256>>>(dst, cnt);
    scan_cnt<<<1, 1024>>>(cnt, off, pos);
    scatter_edges<<<(EE + 255) / 256, 256>>>(dst, pos, order);

    // ---- conversions ----
    for (int i = 0; i < 5; i++) {
        split_weight<<<(NOUT * KPAD + 255) / 256, 256>>>(W1[i], whi + i * WS,       wlo + i * WS,       Kin[i]);
        split_weight<<<(NOUT * KPAD + 255) / 256, 256>>>(W2[i], whi + (5 + i) * WS, wlo + (5 + i) * WS, Kin[i]);
    }
    pack_bias<<<4, 256>>>((const float*)d_in[4],  (const float*)d_in[6],
                          (const float*)d_in[8],  (const float*)d_in[11], bias);
    pack_bias<<<4, 256>>>((const float*)d_in[13], (const float*)d_in[15],
                          (const float*)d_in[17], (const float*)d_in[20], bias + 4 * NOUT);

    split_feat<<<((size_t)EE * KPAD + 255) / 256, 256>>>(ea, ehi, elo, EE, EDD);
    split_feat<<<((size_t)NN * KPAD + 255) / 256, 256>>>(x,  ahi, alo, NN, DNODE);

    // ---- layer 1: edge_dst writes relu+bf16-split of output (layer-2 input) ----
    run_layer(ahi, alo, ehi, elo, whi, wlo, WS, bias, src, off, order,
              q, k, v, e, skip, nullptr, ahi, alo, 1);

    // ---- layer 2: edge_dst writes d_out ----
    run_layer(ahi, alo, ehi, elo, whi + 5 * WS, wlo + 5 * WS, WS, bias + 4 * NOUT,
              src, off, order, q, k, v, e, skip, out, nullptr, nullptr, 0);
}